// round 15
// baseline (speedup 1.0000x reference)
#include <cuda_runtime.h>
#include <cuda_bf16.h>
#include <math.h>
#include <stdint.h>

#define Bq   64
#define Lq   256
#define DINq 768
#define Hq   64
#define Eq   8
#define NT   (Bq * Lq)

typedef unsigned long long ull;

// ---------------- device scratch ----------------
__device__ float g_mean[NT];
__device__ int   g_e1[Bq], g_e2[Bq];
__device__ float g_g1[Bq], g_g2[Bq];
__device__ float g_gbias[Bq * Hq];
__device__ float g_Y  [NT * Hq];
__device__ float g_SH [NT * Hq];
__device__ float g_RGB[NT * Hq];
__device__ float g_T  [NT * 2 * Hq];
// pre-converted bf16 hi/lo weights (uint4 = 8 bf16)
__device__ uint4 g_WcombH[Bq * 6144];
__device__ uint4 g_WcombL[Bq * 6144];
__device__ uint4 g_WshH[6144],  g_WshL[6144];
__device__ uint4 g_WrgbH[6144], g_WrgbL[6144];

// ---------------- helpers ----------------
__device__ __forceinline__ float gelu1(float x) {
    return 0.5f * x * (1.0f + erff(x * 0.7071067811865475f));
}
__device__ __forceinline__ float4 f4add(float4 a, float4 b) {
    return make_float4(a.x + b.x, a.y + b.y, a.z + b.z, a.w + b.w);
}
__device__ __forceinline__ float4 f4mul(float4 a, float4 b) {
    return make_float4(a.x * b.x, a.y * b.y, a.z * b.z, a.w * b.w);
}
__device__ __forceinline__ float4 gelu4(float4 a) {
    return make_float4(gelu1(a.x), gelu1(a.y), gelu1(a.z), gelu1(a.w));
}
__device__ __forceinline__ uint32_t smem_u32(const void* p) {
    uint32_t a;
    asm("{ .reg .u64 t; cvta.to.shared.u64 t, %1; cvt.u32.u64 %0, t; }"
        : "=r"(a) : "l"(p));
    return a;
}
__device__ __forceinline__ uint32_t swz(uint32_t off) {
    return off ^ ((off >> 3) & 0x70u);
}
__device__ __forceinline__ uint32_t pack_split(float f0, float f1, uint32_t& lo) {
    __nv_bfloat16 h0 = __float2bfloat16(f0);
    __nv_bfloat16 h1 = __float2bfloat16(f1);
    __nv_bfloat16 l0 = __float2bfloat16(f0 - __bfloat162float(h0));
    __nv_bfloat16 l1 = __float2bfloat16(f1 - __bfloat162float(h1));
    lo = ((uint32_t)__bfloat16_as_ushort(l1) << 16) | (uint32_t)__bfloat16_as_ushort(l0);
    return ((uint32_t)__bfloat16_as_ushort(h1) << 16) | (uint32_t)__bfloat16_as_ushort(h0);
}
__device__ __forceinline__ void ldsm_x4(uint32_t addr, uint32_t r[4]) {
    asm volatile("ldmatrix.sync.aligned.m8n8.x4.shared.b16 {%0,%1,%2,%3}, [%4];"
                 : "=r"(r[0]), "=r"(r[1]), "=r"(r[2]), "=r"(r[3]) : "r"(addr));
}
__device__ __forceinline__ void ldsm_x2_t(uint32_t addr, uint32_t r[2]) {
    asm volatile("ldmatrix.sync.aligned.m8n8.x2.trans.shared.b16 {%0,%1}, [%2];"
                 : "=r"(r[0]), "=r"(r[1]) : "r"(addr));
}
__device__ __forceinline__ void mma_bf16(float c[4], const uint32_t a[4],
                                         uint32_t b0, uint32_t b1) {
    asm volatile(
        "mma.sync.aligned.m16n8k16.row.col.f32.bf16.bf16.f32 "
        "{%0,%1,%2,%3}, {%4,%5,%6,%7}, {%8,%9}, {%0,%1,%2,%3};"
        : "+f"(c[0]), "+f"(c[1]), "+f"(c[2]), "+f"(c[3])
        : "r"(a[0]), "r"(a[1]), "r"(a[2]), "r"(a[3]), "r"(b0), "r"(b1));
}
#define CP_ASYNC16(saddr, gptr) \
    asm volatile("cp.async.cg.shared.global [%0], [%1], 16;" \
                 :: "r"(saddr), "l"(gptr) : "memory")
#define CP_COMMIT() asm volatile("cp.async.commit_group;" ::: "memory")
#define CP_WAIT0()  asm volatile("cp.async.wait_group 0;" ::: "memory")
// packed f32x2
__device__ __forceinline__ ull fma2(ull a, ull b, ull c) {
    ull d;
    asm("fma.rn.f32x2 %0, %1, %2, %3;" : "=l"(d) : "l"(a), "l"(b), "l"(c));
    return d;
}
__device__ __forceinline__ ull pk2(float x) {
    ull r; unsigned u = __float_as_uint(x);
    asm("mov.b64 %0, {%1, %1};" : "=l"(r) : "r"(u));
    return r;
}
__device__ __forceinline__ float2 unpk(ull v) {
    unsigned lo, hi;
    asm("mov.b64 {%0, %1}, %2;" : "=r"(lo), "=r"(hi) : "l"(v));
    return make_float2(__uint_as_float(lo), __uint_as_float(hi));
}

// ---------------- K0: row mean ----------------
__global__ void k_mean(const float* __restrict__ dte) {
    int w = threadIdx.x >> 5, lane = threadIdx.x & 31;
    int row = blockIdx.x * 8 + w;
    const float* p = dte + (size_t)row * DINq + lane;
    float s = 0.0f;
#pragma unroll
    for (int k = 0; k < DINq / 32; k++) s += p[k * 32];
#pragma unroll
    for (int o = 16; o; o >>= 1) s += __shfl_xor_sync(0xffffffffu, s, o);
    if (lane == 0) g_mean[row] = s * (1.0f / (float)DINq);
}

// ---------------- K1: gating per batch (64 blocks x 256 thr) ----------------
__global__ void k_gate2(const float* __restrict__ w_gate,
                        const float* __restrict__ b_exp) {
    __shared__ float red[8][Eq];
    __shared__ float s_lg[Eq];
    __shared__ int   s_e[2];
    __shared__ float s_g[2];
    int b = blockIdx.x, tid = threadIdx.x;
    int wid = tid >> 5, lane = tid & 31;

    float m = g_mean[b * Lq + tid];
    float lg[Eq];
#pragma unroll
    for (int e = 0; e < Eq; e++) lg[e] = m * __ldg(w_gate + tid * Eq + e);
#pragma unroll
    for (int e = 0; e < Eq; e++) {
#pragma unroll
        for (int o = 16; o; o >>= 1)
            lg[e] += __shfl_xor_sync(0xffffffffu, lg[e], o);
    }
    if (lane == 0)
#pragma unroll
        for (int e = 0; e < Eq; e++) red[wid][e] = lg[e];
    __syncthreads();

    if (tid < Eq) {
        float s = 0.0f;
#pragma unroll
        for (int w = 0; w < 8; w++) s += red[w][tid];
        s_lg[tid] = s;
    }
    __syncthreads();

    if (tid == 0) {
        int e1 = 0;
        for (int e = 1; e < Eq; e++) if (s_lg[e] > s_lg[e1]) e1 = e;
        int e2 = -1;
        for (int e = 0; e < Eq; e++) {
            if (e == e1) continue;
            if (e2 < 0 || s_lg[e] > s_lg[e2]) e2 = e;
        }
        float ex = expf(s_lg[e2] - s_lg[e1]);
        float den = 1.0f / (1.0f + ex);
        float g1 = den, g2 = ex * den;
        g_e1[b] = e1; g_e2[b] = e2; g_g1[b] = g1; g_g2[b] = g2;
        s_e[0] = e1; s_e[1] = e2; s_g[0] = g1; s_g[1] = g2;
    }
    __syncthreads();
    if (tid < Hq)
        g_gbias[b * Hq + tid] = s_g[0] * b_exp[s_e[0] * Hq + tid]
                              + s_g[1] * b_exp[s_e[1] * Hq + tid];
}

// ---------------- K2: weight prep (comb + static + loss) ----------------
__global__ void k_wprep(const float* __restrict__ W_exp,
                        const float* __restrict__ W_sh,
                        const float* __restrict__ W_rgb,
                        float* __restrict__ d_out, int loss_idx) {
    int y = blockIdx.y;
    int idx = blockIdx.x * 256 + threadIdx.x;     // < 6144
    if (y == 64 && blockIdx.x == 0 && threadIdx.x == 0) {
        float imp[Eq], ld[Eq];
#pragma unroll
        for (int e = 0; e < Eq; e++) { imp[e] = 0.0f; ld[e] = 0.0f; }
        for (int b = 0; b < Bq; b++) {
            imp[g_e1[b]] += g_g1[b];
            imp[g_e2[b]] += g_g2[b];
            ld[g_e1[b]] += 1.0f;
            ld[g_e2[b]] += 1.0f;
        }
        float m1 = 0.0f, m2 = 0.0f;
        for (int e = 0; e < Eq; e++) { m1 += imp[e]; m2 += ld[e]; }
        m1 *= (1.0f / Eq); m2 *= (1.0f / Eq);
        float var1 = 0.0f, var2 = 0.0f;
        for (int e = 0; e < Eq; e++) {
            float d1 = imp[e] - m1; var1 += d1 * d1;
            float d2 = ld[e] - m2;  var2 += d2 * d2;
        }
        var1 *= (1.0f / (Eq - 1)); var2 *= (1.0f / (Eq - 1));
        d_out[loss_idx] = 0.01f * (var1 / (m1 * m1 + 1e-10f) +
                                   var2 / (m2 * m2 + 1e-10f));
    }
    float f[8];
    if (y < Bq) {
        float g1 = g_g1[y], g2 = g_g2[y];
        const float* p1 = W_exp + (size_t)g_e1[y] * DINq * Hq + (size_t)idx * 8;
        const float* p2 = W_exp + (size_t)g_e2[y] * DINq * Hq + (size_t)idx * 8;
        float4 a0 = *(const float4*)p1, a1 = *(const float4*)(p1 + 4);
        float4 c0 = *(const float4*)p2, c1 = *(const float4*)(p2 + 4);
        f[0] = g1 * a0.x + g2 * c0.x; f[1] = g1 * a0.y + g2 * c0.y;
        f[2] = g1 * a0.z + g2 * c0.z; f[3] = g1 * a0.w + g2 * c0.w;
        f[4] = g1 * a1.x + g2 * c1.x; f[5] = g1 * a1.y + g2 * c1.y;
        f[6] = g1 * a1.z + g2 * c1.z; f[7] = g1 * a1.w + g2 * c1.w;
    } else {
        const float* src = (y == 65 ? W_rgb : W_sh) + (size_t)idx * 8;
        float4 a0 = *(const float4*)src, a1 = *(const float4*)(src + 4);
        f[0] = a0.x; f[1] = a0.y; f[2] = a0.z; f[3] = a0.w;
        f[4] = a1.x; f[5] = a1.y; f[6] = a1.z; f[7] = a1.w;
    }
    uint32_t hu[4], lu[4];
    hu[0] = pack_split(f[0], f[1], lu[0]);
    hu[1] = pack_split(f[2], f[3], lu[1]);
    hu[2] = pack_split(f[4], f[5], lu[2]);
    hu[3] = pack_split(f[6], f[7], lu[3]);
    uint4 h4 = make_uint4(hu[0], hu[1], hu[2], hu[3]);
    uint4 l4 = make_uint4(lu[0], lu[1], lu[2], lu[3]);
    if (y < Bq)       { g_WcombH[y * 6144 + idx] = h4; g_WcombL[y * 6144 + idx] = l4; }
    else if (y == 64) { g_WshH[idx]  = h4; g_WshL[idx]  = l4; }
    else              { g_WrgbH[idx] = h4; g_WrgbL[idx] = l4; }
}

// ---------------- K3: pipelined mma.sync bf16x3 GEMM (512 thr) + fused preln -
#define BUFSZ  49152u
#define SMEM_MM (2 * 49152)

template <bool JOBA>
__device__ __forceinline__ void gemm_body(
    int job, const float* __restrict__ dte, const float* __restrict__ x,
    const float* __restrict__ b_sh, const float* __restrict__ b_rgb,
    const float* __restrict__ W_px, const float* __restrict__ b_px,
    const float* __restrict__ ln_g, const float* __restrict__ ln_b,
    char* smc, uint32_t sb) {
    int tid = threadIdx.x, lane = tid & 31, wid = tid >> 5;

    const float* Asrc;
    int bb = 0;
    size_t tok0;
    if (JOBA) {
        bb = job >> 2;
        tok0 = (size_t)bb * Lq + (job & 3) * 64;
        Asrc = dte + tok0 * DINq;
    } else {
        tok0 = (size_t)job * 64;
        Asrc = x + tok0 * DINq;
    }

    constexpr int NTL = JOBA ? 4 : 2;
    constexpr uint32_t ROWB = JOBA ? 256u : 128u;
    constexpr int RSH = JOBA ? 8 : 7;
    constexpr uint32_t OFFAL = 8192u;
    constexpr uint32_t OFFBH = 16384u;
    constexpr uint32_t OFFBL = OFFBH + (JOBA ? 16384u : 8192u);

    // 16 warps: 4 m-tiles x 4 n-groups
    int wm = wid & 3, wn = wid >> 2;
    int m_base = wm * 16;
    int n_base = wn * (JOBA ? 32 : 16);

    float c[NTL][4];
#pragma unroll
    for (int nt = 0; nt < NTL; nt++)
#pragma unroll
        for (int j = 0; j < 4; j++) c[nt][j] = 0.0f;

    int lr = lane & 7, sel = lane >> 3;
    int a_row_off = ((sel & 1) << 3) + lr;
    int a_kb_off  = (sel >> 1) << 4;
    int brow = lane & 15;

    int arow = tid >> 3, akseg = tid & 7;          // 8 floats per thread
    const float* asrc_t = Asrc + (size_t)arow * DINq + akseg * 8;
    float areg[8];

    auto issueB = [&](int ch, uint32_t bo) {
        int k0 = ch * 64;
        if (JOBA) {
#pragma unroll
            for (int i = 0; i < 4; i++) {
                int t2 = tid + i * 512;
                int reg = t2 >> 10;
                int r = t2 & 1023;
                int k = r >> 4, seg = r & 15;
                const uint4* g;
                if (seg < 8)
                    g = (reg ? g_WcombL : g_WcombH) + bb * 6144 + (k0 + k) * 8 + seg;
                else
                    g = (reg ? g_WshL : g_WshH) + (k0 + k) * 8 + (seg - 8);
                uint32_t off = (uint32_t)k * ROWB + (uint32_t)seg * 16u;
                off ^= ((off >> RSH) & 7u) << 4;
                CP_ASYNC16(sb + bo + (reg ? OFFBL : OFFBH) + off, g);
            }
        } else {
#pragma unroll
            for (int i = 0; i < 2; i++) {
                int t2 = tid + i * 512;
                int reg = t2 >> 9;
                int r = t2 & 511;
                int k = r >> 3, seg = r & 7;
                const uint4* g = (reg ? g_WrgbL : g_WrgbH) + (k0 + k) * 8 + seg;
                uint32_t off = (uint32_t)k * ROWB + (uint32_t)seg * 16u;
                off ^= ((off >> RSH) & 7u) << 4;
                CP_ASYNC16(sb + bo + (reg ? OFFBL : OFFBH) + off, g);
            }
        }
        CP_COMMIT();
    };
    auto ldgA = [&](int ch) {
        const float* s = asrc_t + ch * 64;
        *(float4*)areg       = *(const float4*)s;
        *(float4*)(areg + 4) = *(const float4*)(s + 4);
    };

    issueB(0, 0u);
    ldgA(0);

    for (int ch = 0; ch < 12; ch++) {
        uint32_t bo = (ch & 1) ? BUFSZ : 0u;

        {
            uint32_t hu[4], lu[4];
            hu[0] = pack_split(areg[0], areg[1], lu[0]);
            hu[1] = pack_split(areg[2], areg[3], lu[1]);
            hu[2] = pack_split(areg[4], areg[5], lu[2]);
            hu[3] = pack_split(areg[6], areg[7], lu[3]);
            uint32_t base = (uint32_t)arow * 128u + (uint32_t)akseg * 16u;
            uint32_t o0 = swz(base);
            *(uint4*)(smc + bo + o0) = make_uint4(hu[0], hu[1], hu[2], hu[3]);
            *(uint4*)(smc + bo + OFFAL + o0) = make_uint4(lu[0], lu[1], lu[2], lu[3]);
        }
        CP_WAIT0();
        __syncthreads();

        if (ch < 11) {
            issueB(ch + 1, (ch & 1) ? 0u : BUFSZ);
            ldgA(ch + 1);
        }

#pragma unroll
        for (int ks = 0; ks < 4; ks++) {
            int kbyte = ks * 32;
            uint32_t ahi[4], alo[4];
            {
                uint32_t ro = (uint32_t)((m_base + a_row_off) * 128
                                         + kbyte + a_kb_off);
                uint32_t so = swz(ro);
                ldsm_x4(sb + bo + so, ahi);
                ldsm_x4(sb + bo + OFFAL + so, alo);
            }
            uint32_t krow = (uint32_t)(ks * 16 + brow) * ROWB;
#pragma unroll
            for (int nt = 0; nt < NTL; nt++) {
                uint32_t boff = krow + (uint32_t)(n_base + nt * 8) * 2u;
                boff ^= ((boff >> RSH) & 7u) << 4;
                uint32_t bh[2], bl[2];
                ldsm_x2_t(sb + bo + OFFBH + boff, bh);
                ldsm_x2_t(sb + bo + OFFBL + boff, bl);
                mma_bf16(c[nt], ahi, bh[0], bh[1]);
                mma_bf16(c[nt], ahi, bl[0], bl[1]);
                mma_bf16(c[nt], alo, bh[0], bh[1]);
            }
        }
    }

    // all warps past all mma -> both smem buffers free for reuse
    __syncthreads();
    float* s_sh = (float*)smc;                          // 64 x 68

    int rg = lane >> 2, tg = lane & 3;
#pragma unroll
    for (int nt = 0; nt < NTL; nt++) {
        int col = n_base + nt * 8 + tg * 2;
        int row0 = m_base + rg;
        float* dst;
        const float* bias;
        int cc;
        if (!JOBA) {
            dst = g_RGB; bias = b_rgb; cc = col;
        } else if (col < 64) {
            dst = g_Y; bias = g_gbias + bb * 64; cc = col;
        } else {
            dst = g_SH; bias = b_sh; cc = col - 64;
        }
        float b0 = bias[cc], b1 = bias[cc + 1];
        float v00 = c[nt][0] + b0, v01 = c[nt][1] + b1;
        float v10 = c[nt][2] + b0, v11 = c[nt][3] + b1;
        float* p0 = dst + (tok0 + row0) * Hq + cc;
        float* p1 = dst + (tok0 + row0 + 8) * Hq + cc;
        p0[0] = v00;  p0[1] = v01;
        p1[0] = v10;  p1[1] = v11;
        if (JOBA && col >= 64) {
            s_sh[row0 * 68 + cc]           = v00;
            s_sh[row0 * 68 + cc + 1]       = v01;
            s_sh[(row0 + 8) * 68 + cc]     = v10;
            s_sh[(row0 + 8) * 68 + cc + 1] = v11;
        }
    }

    if (!JOBA) return;

    // ---- fused preln (1 token per 8-thread group) ----
    float* s_w = (float*)(smc + 17408);                 // 8192 floats
    float* s_t = (float*)(smc + 17408 + 32768);         // 64 x 68

#pragma unroll
    for (int i = 0; i < 4; i++) {
        int idx = tid + i * 512;
        int row = idx >> 5, il = idx & 31;
        int p = (il >> 2) | ((il & 3) << 3);
        ((float4*)s_w)[row * 32 + p] = ((const float4*)W_px)[idx];
    }
    __syncthreads();

    int tok = tid >> 3, sub = tid & 7;
    float va[8];
    {
        const float* pa = s_sh + tok * 68 + sub * 8;
        *(float4*)va       = *(const float4*)pa;
        *(float4*)(va + 4) = *(const float4*)(pa + 4);
    }
    float sa = 0.f, s2a = 0.f;
#pragma unroll
    for (int u = 0; u < 8; u++) { sa += va[u]; s2a += va[u] * va[u]; }
#pragma unroll
    for (int o = 1; o < 8; o <<= 1) {
        sa  += __shfl_xor_sync(0xffffffffu, sa, o);
        s2a += __shfl_xor_sync(0xffffffffu, s2a, o);
    }
    float ma = sa * (1.0f / Hq);
    float ra = rsqrtf(s2a * (1.0f / Hq) - ma * ma + 1e-6f);

    float* tra = s_t + tok * 68;
#pragma unroll
    for (int u = 0; u < 8; u++) {
        float g = __ldg(ln_g + sub * 8 + u), bv = __ldg(ln_b + sub * 8 + u);
        tra[sub * 8 + u] = (va[u] - ma) * ra * g + bv;
    }
    __syncthreads();

    ull acc[8];
    {
        const ulonglong2* bp = (const ulonglong2*)(b_px + sub * 16);
#pragma unroll
        for (int j = 0; j < 4; j++) {
            ulonglong2 bv = __ldg(bp + j);
            acc[2 * j] = bv.x; acc[2 * j + 1] = bv.y;
        }
    }
#pragma unroll 8
    for (int h = 0; h < 64; h++) {
        ull ia = pk2(tra[h]);
        const ulonglong2* wr = (const ulonglong2*)(s_w + h * 128);
#pragma unroll
        for (int j = 0; j < 4; j++) {
            ulonglong2 wv = wr[sub + j * 8];
            acc[2 * j]     = fma2(ia, wv.x, acc[2 * j]);
            acc[2 * j + 1] = fma2(ia, wv.y, acc[2 * j + 1]);
        }
    }
    float* oa = g_T + (tok0 + tok) * 128 + sub * 16;
#pragma unroll
    for (int j = 0; j < 4; j++) {
        float2 f0 = unpk(acc[2 * j]);
        float2 f1 = unpk(acc[2 * j + 1]);
        *(float4*)(oa + j * 4) = make_float4(f0.x, f0.y, f1.x, f1.y);
    }
}

__global__ void __launch_bounds__(512, 2) k_gemm(
    const float* __restrict__ dte, const float* __restrict__ x,
    const float* __restrict__ b_sh, const float* __restrict__ b_rgb,
    const float* __restrict__ W_px, const float* __restrict__ b_px,
    const float* __restrict__ ln_g, const float* __restrict__ ln_b) {
    extern __shared__ char smc[];
    uint32_t sb = smem_u32(smc);
    int b = blockIdx.x;
    if (b & 1)
        gemm_body<false>(b >> 1, dte, x, b_sh, b_rgb, W_px, b_px, ln_g, ln_b, smc, sb);
    else
        gemm_body<true>(b >> 1, dte, x, b_sh, b_rgb, W_px, b_px, ln_g, ln_b, smc, sb);
}

// ---------------- matvec: 8 outputs x 2 tokens, shared weight loads ----------
__device__ __forceinline__ void mm8x2(const float* __restrict__ inA,
                                      const float* __restrict__ inB,
                                      const float* __restrict__ w,
                                      int sub, ull accA[4], ull accB[4]) {
#pragma unroll 8
    for (int h = 0; h < 64; h++) {
        ull ia = pk2(inA[h]);
        ull ib = pk2(inB[h]);
        const ulonglong2* wr = (const ulonglong2*)(w + h * 64);
        ulonglong2 w0 = wr[sub];
        ulonglong2 w1 = wr[sub + 8];
        accA[0] = fma2(ia, w0.x, accA[0]);
        accA[1] = fma2(ia, w0.y, accA[1]);
        accA[2] = fma2(ia, w1.x, accA[2]);
        accA[3] = fma2(ia, w1.y, accA[3]);
        accB[0] = fma2(ib, w0.x, accB[0]);
        accB[1] = fma2(ib, w0.y, accB[1]);
        accB[2] = fma2(ib, w1.x, accB[2]);
        accB[3] = fma2(ib, w1.y, accB[3]);
    }
}
__device__ __forceinline__ void bias_init8(const float* __restrict__ bias,
                                           int sub, ull acc[4]) {
    const ulonglong2* bp = (const ulonglong2*)(bias + sub * 8);
    ulonglong2 b0 = __ldg(bp), b1 = __ldg(bp + 1);
    acc[0] = b0.x; acc[1] = b0.y; acc[2] = b1.x; acc[3] = b1.y;
}
__device__ __forceinline__ void unpack8(const ull acc[4], float o[8]) {
#pragma unroll
    for (int j = 0; j < 4; j++) {
        float2 f = unpk(acc[j]);
        o[2 * j] = f.x; o[2 * j + 1] = f.y;
    }
}

// ---------------- K5: conv + GLU + matmul chain (2 tokens/thread) ------------
#define SMEM_POST 152832

__global__ void __launch_bounds__(256) k_post(
    const float* __restrict__ conv_sh,
    const float* __restrict__ W_pxx,    const float* __restrict__ b_pxx,
    const float* __restrict__ W_dte,    const float* __restrict__ b_dte,
    const float* __restrict__ W_dteall, const float* __restrict__ b_dteall,
    const float* __restrict__ W_fmod,   const float* __restrict__ b_fmod,
    const float* __restrict__ W_fx,     const float* __restrict__ b_fx,
    const float* __restrict__ W_fxx,    const float* __restrict__ b_fxx,
    float* __restrict__ d_out) {
    extern __shared__ float sm[];
    float* s_pxx    = sm;
    float* s_dte    = sm + 4096;
    float* s_dteall = sm + 8192;
    float* s_fmod   = sm + 12288;
    float* s_fx     = sm + 16384;
    float* s_fxx    = sm + 20480;
    float* s_cv     = sm + 24576;
    float* sA       = sm + 25152;
    float* sB       = sA + 4352;
    float* sC       = sB + 4352;

    int tid = threadIdx.x;
    {
        const float* wsrc[6] = {W_pxx, W_dte, W_dteall, W_fmod, W_fx, W_fxx};
#pragma unroll
        for (int m = 0; m < 6; m++)
#pragma unroll
            for (int i = 0; i < 4; i++) {
                int idx = tid + i * 256;
                int row = idx >> 4, il = idx & 15;
                int p = (il >> 1) | ((il & 1) << 3);
                ((float4*)(sm + m * 4096))[row * 16 + p] =
                    ((const float4*)wsrc[m])[idx];
            }
        for (int i = tid; i < 576; i += 256) {
            int tap = i >> 6, h = i & 63;
            s_cv[i] = conv_sh[h * 9 + tap];
        }
    }
    __syncthreads();

    int tok = tid >> 3, sub = tid & 7;
    int ta = blockIdx.x * 64 + tok;
    int tb = ta + 32;
    float* rAa = sA + tok * 68;
    float* rBa = sB + tok * 68;
    float* rCa = sC + tok * 68;
    float* rAb = sA + (tok + 32) * 68;
    float* rBb = sB + (tok + 32) * 68;
    float* rCb = sC + (tok + 32) * 68;
    int h0 = sub * 8;

    *(float4*)(rCa + h0)     = *(const float4*)(g_Y + (size_t)ta * 64 + h0);
    *(float4*)(rCa + h0 + 4) = *(const float4*)(g_Y + (size_t)ta * 64 + h0 + 4);
    *(float4*)(rCb + h0)     = *(const float4*)(g_Y + (size_t)tb * 64 + h0);
    *(float4*)(rCb + h0 + 4) = *(const float4*)(g_Y + (size_t)tb * 64 + h0 + 4);

#pragma unroll
    for (int tt = 0; tt < 2; tt++) {
        int t = tt ? tb : ta;
        float* rA = tt ? rAb : rAa;
        int l = t & 255, ii = l >> 4, jj = l & 15;
        float4 a0 = make_float4(0.f, 0.f, 0.f, 0.f);
        float4 a1 = make_float4(0.f, 0.f, 0.f, 0.f);
#pragma unroll
        for (int tap = 0; tap < 9; tap++) {
            int di = tap / 3 - 1, dj = tap % 3 - 1;
            int ni = ii + di, nj = jj + dj;
            if (ni < 0 || ni > 15 || nj < 0 || nj > 15) continue;
            const float* np = g_T + (size_t)(t + di * 16 + dj) * 128 + h0;
            float4 v0 = *(const float4*)np;
            float4 v1 = *(const float4*)(np + 4);
            float4 w0 = *(const float4*)(s_cv + tap * 64 + h0);
            float4 w1 = *(const float4*)(s_cv + tap * 64 + h0 + 4);
            a0 = f4add(a0, f4mul(v0, w0));
            a1 = f4add(a1, f4mul(v1, w1));
        }
        float4 t20 = *(const float4*)(g_T + (size_t)t * 128 + 64 + h0);
        float4 t21 = *(const float4*)(g_T + (size_t)t * 128 + 64 + h0 + 4);
        *(float4*)(rA + h0)     = f4mul(gelu4(a0), t20);
        *(float4*)(rA + h0 + 4) = f4mul(gelu4(a1), t21);
    }
    __syncwarp();

    {
        ull aa[4], ab[4];
        bias_init8(b_pxx, sub, aa);
#pragma unroll
        for (int j = 0; j < 4; j++) ab[j] = aa[j];
        mm8x2(rAa, rAb, s_pxx, sub, aa, ab);
        float oa[8], ob[8];
        unpack8(aa, oa); unpack8(ab, ob);
        float4 s0 = *(const float4*)(g_SH + (size_t)ta * 64 + h0);
        float4 s1 = *(const float4*)(g_SH + (size_t)ta * 64 + h0 + 4);
        *(float4*)(rBa + h0)     = f4add(*(float4*)oa, s0);
        *(float4*)(rBa + h0 + 4) = f4add(*(float4*)(oa + 4), s1);
        float4 u0 = *(const float4*)(g_SH + (size_t)tb * 64 + h0);
        float4 u1 = *(const float4*)(g_SH + (size_t)tb * 64 + h0 + 4);
        *(float4*)(rBb + h0)     = f4add(*(float4*)ob, u0);
        *(float4*)(rBb + h0 + 4) = f4add(*(float4*)(ob + 4), u1);
    }
    __syncwarp();

    {
        ull aa[4], ab[4];
        bias_init8(b_dte, sub, aa);
#pragma unroll
        for (int j = 0; j < 4; j++) ab[j] = aa[j];
        mm8x2(rCa, rCb, s_dte, sub, aa, ab);
        mm8x2(rBa, rBb, s_dteall, sub, aa, ab);
        float oa[8], ob[8];
        unpack8(aa, oa); unpack8(ab, ob);
#pragma unroll
        for (int u = 0; u < 8; u++) {
            float bd = __ldg(b_dteall + h0 + u);
            oa[u] = gelu1(oa[u] + bd);
            ob[u] = gelu1(ob[u] + bd);
        }
        *(float4*)(rAa + h0)     = *(float4*)oa;
        *(float4*)(rAa + h0 + 4) = *(float4*)(oa + 4);
        *(float4*)(rAb + h0)     = *(float4*)ob;
        *(float4*)(rAb + h0 + 4) = *(float4*)(ob + 4);
    }
    __syncwarp();

    float rgva[8], rgvb[8];
    {
        ull aa[4], ab[4];
        bias_init8(b_fmod, sub, aa);
#pragma unroll
        for (int j = 0; j < 4; j++) ab[j] = aa[j];
        mm8x2(rAa, rAb, s_fmod, sub, aa, ab);
        float oa[8], ob[8];
        unpack8(aa, oa); unpack8(ab, ob);
#pragma unroll
        for (int u = 0; u < 8; u++) { oa[u] = gelu1(oa[u]); ob[u] = gelu1(ob[u]); }
        *(float4*)(rBa + h0)     = *(float4*)oa;
        *(float4*)(rBa + h0 + 4) = *(float4*)(oa + 4);
        *(float4*)(rBb + h0)     = *(float4*)ob;
        *(float4*)(rBb + h0 + 4) = *(float4*)(ob + 4);
        *(float4*)rgva       = *(const float4*)(g_RGB + (size_t)ta * 64 + h0);
        *(float4*)(rgva + 4) = *(const float4*)(g_RGB + (size_t)ta * 64 + h0 + 4);
        *(float4*)rgvb       = *(const float4*)(g_RGB + (size_t)tb * 64 + h0);
        *(float4*)(rgvb + 4) = *(const float4*)(g_RGB + (size_t)tb * 64 + h0 + 4);
#pragma unroll
        for (int u = 0; u < 8; u++) {
            rCa[h0 + u] = gelu1(rgva[u]);
            rCb[h0 + u] = gelu1(rgvb[u]);
        }
    }
    __syncwarp();

    {
        ull aa[4], ab[4];
        bias_init8(b_fx, sub, aa);
#pragma unroll
        for (int j = 0; j < 4; j++) ab[j] = aa[j];
        mm8x2(rCa, rCb, s_fx, sub, aa, ab);
        float oa[8], ob[8];
        unpack8(aa, oa); unpack8(ab, ob);
#pragma unroll
        for (int u = 0; u < 8; u++) {
            oa[u] *= rBa[h0 + u];
            ob[u] *= rBb[h0 + u];
        }
        *(float4*)(rAa + h0)     = *(float4*)oa;
        *(float4*)(rAa + h0 + 4) = *(float4*)(oa + 4);
        *(float4*)(rAb + h0)     = *(float4*)ob;
        *(float4*)(rAb + h0 + 4) = *(float4*)(ob + 4);
    }
    __syncwarp();

    {
        ull aa[4], ab[4];
        bias_init8(b_fxx, sub, aa);
#pragma unroll
        for (int j = 0; j < 4; j++) ab[j] = aa[j];
        mm8x2(rAa, rAb, s_fxx, sub, aa, ab);
        float oa[8], ob[8];
        unpack8(aa, oa); unpack8(ab, ob);
        float4 o0 = f4add(*(float4*)oa, *(float4*)rgva);
        float4 o1 = f4add(*(float4*)(oa + 4), *(float4*)(rgva + 4));
        *(float4*)(d_out + (size_t)ta * 64 + h0)     = o0;
        *(float4*)(d_out + (size_t)ta * 64 + h0 + 4) = o1;
        float4 p0 = f4add(*(float4*)ob, *(float4*)rgvb);
        float4 p1 = f4add(*(float4*)(ob + 4), *(float4*)(rgvb + 4));
        *(float4*)(d_out + (size_t)tb * 64 + h0)     = p0;
        *(float4*)(d_out + (size_t)tb * 64 + h0 + 4) = p1;
    }
}

// ---------------- host launcher ----------------
extern "C" void kernel_launch(void* const* d_in, const int* in_sizes, int n_in,
                              void* d_out, int out_size) {
    const float* x        = (const float*)d_in[0];
    const float* dte      = (const float*)d_in[1];
    const float* w_gate   = (const float*)d_in[2];
    const float* W_exp    = (const float*)d_in[3];
    const float* b_exp    = (const float*)d_in[4];
    const float* W_sh     = (const float*)d_in[5];
    const float* b_sh     = (const float*)d_in[6];
    const float* ln_g     = (const float*)d_in[7];
    const float* ln_b     = (const float*)d_in[8];
    const float* W_px     = (const float*)d_in[9];
    const float* b_px     = (const float*)d_in[10];
    const float* conv_sh  = (const float*)d_in[11];
    const float* W_pxx    = (const float*)d_in[12];
    const float* b_pxx    = (const float*)d_in[13];
    const float* W_dte    = (const float*)d_in[14];
    const float* b_dte    = (const float*)d_in[15];
    const float* W_dteall = (const float*)d_in[16];
    const float* b_dteall = (const float*)d_in[17];
    const float* W_rgb    = (const float*)d_in[18];
    const float* b_rgb    = (const float*)d_in[19];
    const float* W_fx     = (const float*)d_in[20];
    const float* b_fx     = (const float*)d_in[21];
    const float* W_fmod   = (const float*)d_in[22];
    const float* b_fmod   = (const float*)d_in[23];
    const float* W_fxx    = (const float*)d_in[24];
    const float* b_fxx    = (const float*)d_in[25];
    float* out = (float*)d_out;

    cudaFuncSetAttribute(k_gemm, cudaFuncAttributeMaxDynamicSharedMemorySize, SMEM_MM);
    cudaFuncSetAttribute(k_post, cudaFuncAttributeMaxDynamicSharedMemorySize, SMEM_POST);

    k_mean<<<NT / 8, 256>>>(dte);
    k_gate2<<<Bq, 256>>>(w_gate, b_exp);
    k_wprep<<<dim3(24, 66), 256>>>(W_exp, W_sh, W_rgb, out, out_size - 1);

    k_gemm<<<512, 512, SMEM_MM>>>(dte, x, b_sh, b_rgb, W_px, b_px, ln_g, ln_b);

    k_post<<<256, 256, SMEM_POST>>>(conv_sh,
                                    W_pxx, b_pxx, W_dte, b_dte, W_dteall, b_dteall,
                                    W_fmod, b_fmod, W_fx, b_fx, W_fxx, b_fxx,
                                    out);
}

// round 16
// speedup vs baseline: 1.0756x; 1.0756x over previous
#include <cuda_runtime.h>
#include <cuda_bf16.h>
#include <math.h>
#include <stdint.h>

#define Bq   64
#define Lq   256
#define DINq 768
#define Hq   64
#define Eq   8
#define NT   (Bq * Lq)

typedef unsigned long long ull;

// ---------------- device scratch ----------------
__device__ float g_mean[NT];
__device__ int   g_e1[Bq], g_e2[Bq];
__device__ float g_g1[Bq], g_g2[Bq];
__device__ float g_gbias[Bq * Hq];
__device__ float g_Y  [NT * Hq];
__device__ float g_SH [NT * Hq];
__device__ float g_RGB[NT * Hq];
__device__ float g_T  [NT * 2 * Hq];
// pre-converted bf16 hi/lo weights (uint4 = 8 bf16)
__device__ uint4 g_WcombH[Bq * 6144];
__device__ uint4 g_WcombL[Bq * 6144];
__device__ uint4 g_WshH[6144],  g_WshL[6144];
__device__ uint4 g_WrgbH[6144], g_WrgbL[6144];

// ---------------- helpers ----------------
__device__ __forceinline__ float gelu1(float x) {
    return 0.5f * x * (1.0f + erff(x * 0.7071067811865475f));
}
__device__ __forceinline__ float4 f4add(float4 a, float4 b) {
    return make_float4(a.x + b.x, a.y + b.y, a.z + b.z, a.w + b.w);
}
__device__ __forceinline__ float4 f4mul(float4 a, float4 b) {
    return make_float4(a.x * b.x, a.y * b.y, a.z * b.z, a.w * b.w);
}
__device__ __forceinline__ float4 gelu4(float4 a) {
    return make_float4(gelu1(a.x), gelu1(a.y), gelu1(a.z), gelu1(a.w));
}
__device__ __forceinline__ uint32_t smem_u32(const void* p) {
    uint32_t a;
    asm("{ .reg .u64 t; cvta.to.shared.u64 t, %1; cvt.u32.u64 %0, t; }"
        : "=r"(a) : "l"(p));
    return a;
}
__device__ __forceinline__ uint32_t swz(uint32_t off) {
    return off ^ ((off >> 3) & 0x70u);
}
__device__ __forceinline__ uint32_t pack_split(float f0, float f1, uint32_t& lo) {
    __nv_bfloat16 h0 = __float2bfloat16(f0);
    __nv_bfloat16 h1 = __float2bfloat16(f1);
    __nv_bfloat16 l0 = __float2bfloat16(f0 - __bfloat162float(h0));
    __nv_bfloat16 l1 = __float2bfloat16(f1 - __bfloat162float(h1));
    lo = ((uint32_t)__bfloat16_as_ushort(l1) << 16) | (uint32_t)__bfloat16_as_ushort(l0);
    return ((uint32_t)__bfloat16_as_ushort(h1) << 16) | (uint32_t)__bfloat16_as_ushort(h0);
}
__device__ __forceinline__ void ldsm_x4(uint32_t addr, uint32_t r[4]) {
    asm volatile("ldmatrix.sync.aligned.m8n8.x4.shared.b16 {%0,%1,%2,%3}, [%4];"
                 : "=r"(r[0]), "=r"(r[1]), "=r"(r[2]), "=r"(r[3]) : "r"(addr));
}
__device__ __forceinline__ void ldsm_x2_t(uint32_t addr, uint32_t r[2]) {
    asm volatile("ldmatrix.sync.aligned.m8n8.x2.trans.shared.b16 {%0,%1}, [%2];"
                 : "=r"(r[0]), "=r"(r[1]) : "r"(addr));
}
__device__ __forceinline__ void mma_bf16(float c[4], const uint32_t a[4],
                                         uint32_t b0, uint32_t b1) {
    asm volatile(
        "mma.sync.aligned.m16n8k16.row.col.f32.bf16.bf16.f32 "
        "{%0,%1,%2,%3}, {%4,%5,%6,%7}, {%8,%9}, {%0,%1,%2,%3};"
        : "+f"(c[0]), "+f"(c[1]), "+f"(c[2]), "+f"(c[3])
        : "r"(a[0]), "r"(a[1]), "r"(a[2]), "r"(a[3]), "r"(b0), "r"(b1));
}
#define CP_ASYNC16(saddr, gptr) \
    asm volatile("cp.async.cg.shared.global [%0], [%1], 16;" \
                 :: "r"(saddr), "l"(gptr) : "memory")
#define CP_COMMIT() asm volatile("cp.async.commit_group;" ::: "memory")
#define CP_WAIT0()  asm volatile("cp.async.wait_group 0;" ::: "memory")
// packed f32x2
__device__ __forceinline__ ull fma2(ull a, ull b, ull c) {
    ull d;
    asm("fma.rn.f32x2 %0, %1, %2, %3;" : "=l"(d) : "l"(a), "l"(b), "l"(c));
    return d;
}
__device__ __forceinline__ ull pk2(float x) {
    ull r; unsigned u = __float_as_uint(x);
    asm("mov.b64 %0, {%1, %1};" : "=l"(r) : "r"(u));
    return r;
}
__device__ __forceinline__ float2 unpk(ull v) {
    unsigned lo, hi;
    asm("mov.b64 {%0, %1}, %2;" : "=r"(lo), "=r"(hi) : "l"(v));
    return make_float2(__uint_as_float(lo), __uint_as_float(hi));
}

// ---------------- K0: row mean ----------------
__global__ void k_mean(const float* __restrict__ dte) {
    int w = threadIdx.x >> 5, lane = threadIdx.x & 31;
    int row = blockIdx.x * 8 + w;
    const float* p = dte + (size_t)row * DINq + lane;
    float s = 0.0f;
#pragma unroll
    for (int k = 0; k < DINq / 32; k++) s += p[k * 32];
#pragma unroll
    for (int o = 16; o; o >>= 1) s += __shfl_xor_sync(0xffffffffu, s, o);
    if (lane == 0) g_mean[row] = s * (1.0f / (float)DINq);
}

// ---------------- K1: gating per batch (64 blocks x 256 thr) ----------------
__global__ void k_gate2(const float* __restrict__ w_gate,
                        const float* __restrict__ b_exp) {
    __shared__ float red[8][Eq];
    __shared__ float s_lg[Eq];
    __shared__ int   s_e[2];
    __shared__ float s_g[2];
    int b = blockIdx.x, tid = threadIdx.x;
    int wid = tid >> 5, lane = tid & 31;

    float m = g_mean[b * Lq + tid];
    float lg[Eq];
#pragma unroll
    for (int e = 0; e < Eq; e++) lg[e] = m * __ldg(w_gate + tid * Eq + e);
#pragma unroll
    for (int e = 0; e < Eq; e++) {
#pragma unroll
        for (int o = 16; o; o >>= 1)
            lg[e] += __shfl_xor_sync(0xffffffffu, lg[e], o);
    }
    if (lane == 0)
#pragma unroll
        for (int e = 0; e < Eq; e++) red[wid][e] = lg[e];
    __syncthreads();

    if (tid < Eq) {
        float s = 0.0f;
#pragma unroll
        for (int w = 0; w < 8; w++) s += red[w][tid];
        s_lg[tid] = s;
    }
    __syncthreads();

    if (tid == 0) {
        int e1 = 0;
        for (int e = 1; e < Eq; e++) if (s_lg[e] > s_lg[e1]) e1 = e;
        int e2 = -1;
        for (int e = 0; e < Eq; e++) {
            if (e == e1) continue;
            if (e2 < 0 || s_lg[e] > s_lg[e2]) e2 = e;
        }
        float ex = expf(s_lg[e2] - s_lg[e1]);
        float den = 1.0f / (1.0f + ex);
        float g1 = den, g2 = ex * den;
        g_e1[b] = e1; g_e2[b] = e2; g_g1[b] = g1; g_g2[b] = g2;
        s_e[0] = e1; s_e[1] = e2; s_g[0] = g1; s_g[1] = g2;
    }
    __syncthreads();
    if (tid < Hq)
        g_gbias[b * Hq + tid] = s_g[0] * b_exp[s_e[0] * Hq + tid]
                              + s_g[1] * b_exp[s_e[1] * Hq + tid];
}

// ---------------- K2: weight prep (comb + static + loss) ----------------
__global__ void k_wprep(const float* __restrict__ W_exp,
                        const float* __restrict__ W_sh,
                        const float* __restrict__ W_rgb,
                        float* __restrict__ d_out, int loss_idx) {
    int y = blockIdx.y;
    int idx = blockIdx.x * 256 + threadIdx.x;     // < 6144
    if (y == 64 && blockIdx.x == 0 && threadIdx.x == 0) {
        float imp[Eq], ld[Eq];
#pragma unroll
        for (int e = 0; e < Eq; e++) { imp[e] = 0.0f; ld[e] = 0.0f; }
        for (int b = 0; b < Bq; b++) {
            imp[g_e1[b]] += g_g1[b];
            imp[g_e2[b]] += g_g2[b];
            ld[g_e1[b]] += 1.0f;
            ld[g_e2[b]] += 1.0f;
        }
        float m1 = 0.0f, m2 = 0.0f;
        for (int e = 0; e < Eq; e++) { m1 += imp[e]; m2 += ld[e]; }
        m1 *= (1.0f / Eq); m2 *= (1.0f / Eq);
        float var1 = 0.0f, var2 = 0.0f;
        for (int e = 0; e < Eq; e++) {
            float d1 = imp[e] - m1; var1 += d1 * d1;
            float d2 = ld[e] - m2;  var2 += d2 * d2;
        }
        var1 *= (1.0f / (Eq - 1)); var2 *= (1.0f / (Eq - 1));
        d_out[loss_idx] = 0.01f * (var1 / (m1 * m1 + 1e-10f) +
                                   var2 / (m2 * m2 + 1e-10f));
    }
    float f[8];
    if (y < Bq) {
        float g1 = g_g1[y], g2 = g_g2[y];
        const float* p1 = W_exp + (size_t)g_e1[y] * DINq * Hq + (size_t)idx * 8;
        const float* p2 = W_exp + (size_t)g_e2[y] * DINq * Hq + (size_t)idx * 8;
        float4 a0 = *(const float4*)p1, a1 = *(const float4*)(p1 + 4);
        float4 c0 = *(const float4*)p2, c1 = *(const float4*)(p2 + 4);
        f[0] = g1 * a0.x + g2 * c0.x; f[1] = g1 * a0.y + g2 * c0.y;
        f[2] = g1 * a0.z + g2 * c0.z; f[3] = g1 * a0.w + g2 * c0.w;
        f[4] = g1 * a1.x + g2 * c1.x; f[5] = g1 * a1.y + g2 * c1.y;
        f[6] = g1 * a1.z + g2 * c1.z; f[7] = g1 * a1.w + g2 * c1.w;
    } else {
        const float* src = (y == 65 ? W_rgb : W_sh) + (size_t)idx * 8;
        float4 a0 = *(const float4*)src, a1 = *(const float4*)(src + 4);
        f[0] = a0.x; f[1] = a0.y; f[2] = a0.z; f[3] = a0.w;
        f[4] = a1.x; f[5] = a1.y; f[6] = a1.z; f[7] = a1.w;
    }
    uint32_t hu[4], lu[4];
    hu[0] = pack_split(f[0], f[1], lu[0]);
    hu[1] = pack_split(f[2], f[3], lu[1]);
    hu[2] = pack_split(f[4], f[5], lu[2]);
    hu[3] = pack_split(f[6], f[7], lu[3]);
    uint4 h4 = make_uint4(hu[0], hu[1], hu[2], hu[3]);
    uint4 l4 = make_uint4(lu[0], lu[1], lu[2], lu[3]);
    if (y < Bq)       { g_WcombH[y * 6144 + idx] = h4; g_WcombL[y * 6144 + idx] = l4; }
    else if (y == 64) { g_WshH[idx]  = h4; g_WshL[idx]  = l4; }
    else              { g_WrgbH[idx] = h4; g_WrgbL[idx] = l4; }
}

// ---------------- K3: pipelined mma.sync bf16x3 GEMM, M=64 tiles (R12) -------
#define BUFSZ  49152u
#define SMEM_MM (2 * 49152)

template <bool JOBA>
__device__ __forceinline__ void gemm_body(
    int job, const float* __restrict__ dte, const float* __restrict__ x,
    const float* __restrict__ b_sh, const float* __restrict__ b_rgb,
    char* smc, uint32_t sb) {
    int tid = threadIdx.x, lane = tid & 31, wid = tid >> 5;

    const float* Asrc;
    int bb = 0;
    size_t tok0;
    if (JOBA) {
        bb = job >> 2;
        tok0 = (size_t)bb * Lq + (job & 3) * 64;
        Asrc = dte + tok0 * DINq;
    } else {
        tok0 = (size_t)job * 64;
        Asrc = x + tok0 * DINq;
    }

    constexpr int NTL = JOBA ? 4 : 2;
    constexpr uint32_t ROWB = JOBA ? 256u : 128u;
    constexpr int RSH = JOBA ? 8 : 7;
    constexpr uint32_t OFFAL = 8192u;
    constexpr uint32_t OFFBH = 16384u;
    constexpr uint32_t OFFBL = OFFBH + (JOBA ? 16384u : 8192u);

    int wm = wid & 1, wn = wid >> 1;
    int m_base = wm * 32;
    int n_base = wn * (JOBA ? 32 : 16);

    float c[2][NTL][4];
#pragma unroll
    for (int mt = 0; mt < 2; mt++)
#pragma unroll
        for (int nt = 0; nt < NTL; nt++)
#pragma unroll
            for (int j = 0; j < 4; j++) c[mt][nt][j] = 0.0f;

    int lr = lane & 7, sel = lane >> 3;
    int a_row_off = ((sel & 1) << 3) + lr;
    int a_kb_off  = (sel >> 1) << 4;
    int brow = lane & 15;

    int arow = tid >> 2, akseg = tid & 3;
    const float* asrc_t = Asrc + (size_t)arow * DINq + akseg * 16;
    float areg[16];

    auto issueB = [&](int ch, uint32_t bo) {
        int k0 = ch * 64;
        if (JOBA) {
#pragma unroll
            for (int i = 0; i < 8; i++) {
                int t2 = tid + i * 256;
                int reg = t2 >> 10;
                int r = t2 & 1023;
                int k = r >> 4, seg = r & 15;
                const uint4* g;
                if (seg < 8)
                    g = (reg ? g_WcombL : g_WcombH) + bb * 6144 + (k0 + k) * 8 + seg;
                else
                    g = (reg ? g_WshL : g_WshH) + (k0 + k) * 8 + (seg - 8);
                uint32_t off = (uint32_t)k * ROWB + (uint32_t)seg * 16u;
                off ^= ((off >> RSH) & 7u) << 4;
                CP_ASYNC16(sb + bo + (reg ? OFFBL : OFFBH) + off, g);
            }
        } else {
#pragma unroll
            for (int i = 0; i < 4; i++) {
                int t2 = tid + i * 256;
                int reg = t2 >> 9;
                int r = t2 & 511;
                int k = r >> 3, seg = r & 7;
                const uint4* g = (reg ? g_WrgbL : g_WrgbH) + (k0 + k) * 8 + seg;
                uint32_t off = (uint32_t)k * ROWB + (uint32_t)seg * 16u;
                off ^= ((off >> RSH) & 7u) << 4;
                CP_ASYNC16(sb + bo + (reg ? OFFBL : OFFBH) + off, g);
            }
        }
        CP_COMMIT();
    };
    auto ldgA = [&](int ch) {
        const float* s = asrc_t + ch * 64;
#pragma unroll
        for (int j = 0; j < 4; j++)
            *(float4*)(areg + j * 4) = *(const float4*)(s + j * 4);
    };

    issueB(0, 0u);
    ldgA(0);

    for (int ch = 0; ch < 12; ch++) {
        uint32_t bo = (ch & 1) ? BUFSZ : 0u;

        {
            uint32_t hu[8], lu[8];
#pragma unroll
            for (int j = 0; j < 4; j++) {
                hu[j * 2]     = pack_split(areg[j * 4],     areg[j * 4 + 1], lu[j * 2]);
                hu[j * 2 + 1] = pack_split(areg[j * 4 + 2], areg[j * 4 + 3], lu[j * 2 + 1]);
            }
            uint32_t base = (uint32_t)arow * 128u + (uint32_t)akseg * 32u;
            uint32_t o0 = swz(base), o1 = swz(base + 16u);
            *(uint4*)(smc + bo + o0) = make_uint4(hu[0], hu[1], hu[2], hu[3]);
            *(uint4*)(smc + bo + o1) = make_uint4(hu[4], hu[5], hu[6], hu[7]);
            *(uint4*)(smc + bo + OFFAL + o0) = make_uint4(lu[0], lu[1], lu[2], lu[3]);
            *(uint4*)(smc + bo + OFFAL + o1) = make_uint4(lu[4], lu[5], lu[6], lu[7]);
        }
        CP_WAIT0();
        __syncthreads();

        if (ch < 11) {
            issueB(ch + 1, (ch & 1) ? 0u : BUFSZ);
            ldgA(ch + 1);
        }

#pragma unroll
        for (int ks = 0; ks < 4; ks++) {
            int kbyte = ks * 32;
            uint32_t ahi[2][4], alo[2][4];
#pragma unroll
            for (int mt = 0; mt < 2; mt++) {
                uint32_t ro = (uint32_t)((m_base + mt * 16 + a_row_off) * 128
                                         + kbyte + a_kb_off);
                uint32_t so = swz(ro);
                ldsm_x4(sb + bo + so, ahi[mt]);
                ldsm_x4(sb + bo + OFFAL + so, alo[mt]);
            }
            uint32_t krow = (uint32_t)(ks * 16 + brow) * ROWB;
#pragma unroll
            for (int nt = 0; nt < NTL; nt++) {
                uint32_t boff = krow + (uint32_t)(n_base + nt * 8) * 2u;
                boff ^= ((boff >> RSH) & 7u) << 4;
                uint32_t bh[2], bl[2];
                ldsm_x2_t(sb + bo + OFFBH + boff, bh);
                ldsm_x2_t(sb + bo + OFFBL + boff, bl);
#pragma unroll
                for (int mt = 0; mt < 2; mt++) {
                    mma_bf16(c[mt][nt], ahi[mt], bh[0], bh[1]);
                    mma_bf16(c[mt][nt], ahi[mt], bl[0], bl[1]);
                    mma_bf16(c[mt][nt], alo[mt], bh[0], bh[1]);
                }
            }
        }
    }

    int rg = lane >> 2, tg = lane & 3;
#pragma unroll
    for (int mt = 0; mt < 2; mt++) {
#pragma unroll
        for (int nt = 0; nt < NTL; nt++) {
            int col = n_base + nt * 8 + tg * 2;
            int row0 = m_base + mt * 16 + rg;
            float* dst;
            const float* bias;
            int cc;
            if (!JOBA) {
                dst = g_RGB; bias = b_rgb; cc = col;
            } else if (col < 64) {
                dst = g_Y; bias = g_gbias + bb * 64; cc = col;
            } else {
                dst = g_SH; bias = b_sh; cc = col - 64;
            }
            float b0 = bias[cc], b1 = bias[cc + 1];
            float* p0 = dst + (tok0 + row0) * Hq + cc;
            float* p1 = dst + (tok0 + row0 + 8) * Hq + cc;
            p0[0] = c[mt][nt][0] + b0;  p0[1] = c[mt][nt][1] + b1;
            p1[0] = c[mt][nt][2] + b0;  p1[1] = c[mt][nt][3] + b1;
        }
    }
}

__global__ void __launch_bounds__(256, 2) k_gemm(
    const float* __restrict__ dte, const float* __restrict__ x,
    const float* __restrict__ b_sh, const float* __restrict__ b_rgb) {
    extern __shared__ char smc[];
    uint32_t sb = smem_u32(smc);
    int b = blockIdx.x;
    if (b & 1)
        gemm_body<false>(b >> 1, dte, x, b_sh, b_rgb, smc, sb);
    else
        gemm_body<true>(b >> 1, dte, x, b_sh, b_rgb, smc, sb);
}

// ---------------- K4: LayerNorm + W_px (8 thr/token, 2 tokens/thread) -------
__global__ void __launch_bounds__(256) k_preln(
    const float* __restrict__ W_px, const float* __restrict__ b_px,
    const float* __restrict__ ln_g, const float* __restrict__ ln_b) {
    extern __shared__ float sm[];
    float* s_w = sm;            // 64 x 128, chunk-transposed
    float* s_t = sm + 8192;     // 64 tokens x 68

    int tid = threadIdx.x;
#pragma unroll
    for (int i = 0; i < 8; i++) {
        int idx = tid + i * 256;
        int row = idx >> 5, il = idx & 31;
        int p = (il >> 2) | ((il & 3) << 3);
        ((float4*)s_w)[row * 32 + p] = ((const float4*)W_px)[idx];
    }

    int tok = tid >> 3, sub = tid & 7;
    int ta = blockIdx.x * 64 + tok;
    int tb = ta + 32;

    float va[8], vb[8];
    {
        const float* pa = g_SH + (size_t)ta * Hq + sub * 8;
        const float* pb = g_SH + (size_t)tb * Hq + sub * 8;
        *(float4*)va       = *(const float4*)pa;
        *(float4*)(va + 4) = *(const float4*)(pa + 4);
        *(float4*)vb       = *(const float4*)pb;
        *(float4*)(vb + 4) = *(const float4*)(pb + 4);
    }
    float sa = 0.f, s2a = 0.f, sbm = 0.f, s2b = 0.f;
#pragma unroll
    for (int u = 0; u < 8; u++) {
        sa += va[u]; s2a += va[u] * va[u];
        sbm += vb[u]; s2b += vb[u] * vb[u];
    }
#pragma unroll
    for (int o = 1; o < 8; o <<= 1) {
        sa  += __shfl_xor_sync(0xffffffffu, sa, o);
        s2a += __shfl_xor_sync(0xffffffffu, s2a, o);
        sbm += __shfl_xor_sync(0xffffffffu, sbm, o);
        s2b += __shfl_xor_sync(0xffffffffu, s2b, o);
    }
    float ma = sa * (1.0f / Hq), mb = sbm * (1.0f / Hq);
    float ra = rsqrtf(s2a * (1.0f / Hq) - ma * ma + 1e-6f);
    float rb = rsqrtf(s2b * (1.0f / Hq) - mb * mb + 1e-6f);

    float* tra = s_t + tok * 68;
    float* trb = s_t + (tok + 32) * 68;
#pragma unroll
    for (int u = 0; u < 8; u++) {
        float g = __ldg(ln_g + sub * 8 + u), bv = __ldg(ln_b + sub * 8 + u);
        tra[sub * 8 + u] = (va[u] - ma) * ra * g + bv;
        trb[sub * 8 + u] = (vb[u] - mb) * rb * g + bv;
    }
    __syncthreads();

    ull acc[16];
    {
        const ulonglong2* bp = (const ulonglong2*)(b_px + sub * 16);
#pragma unroll
        for (int j = 0; j < 4; j++) {
            ulonglong2 bv = __ldg(bp + j);
            acc[2 * j] = bv.x;      acc[2 * j + 1] = bv.y;
            acc[8 + 2 * j] = bv.x;  acc[8 + 2 * j + 1] = bv.y;
        }
    }
#pragma unroll 4
    for (int h = 0; h < 64; h++) {
        ull ia = pk2(tra[h]);
        ull ib = pk2(trb[h]);
        const ulonglong2* wr = (const ulonglong2*)(s_w + h * 128);
#pragma unroll
        for (int j = 0; j < 4; j++) {
            ulonglong2 wv = wr[sub + j * 8];
            acc[2 * j]         = fma2(ia, wv.x, acc[2 * j]);
            acc[2 * j + 1]     = fma2(ia, wv.y, acc[2 * j + 1]);
            acc[8 + 2 * j]     = fma2(ib, wv.x, acc[8 + 2 * j]);
            acc[8 + 2 * j + 1] = fma2(ib, wv.y, acc[8 + 2 * j + 1]);
        }
    }
    float* oa = g_T + (size_t)ta * 128 + sub * 16;
    float* ob = g_T + (size_t)tb * 128 + sub * 16;
#pragma unroll
    for (int j = 0; j < 4; j++) {
        float2 f0 = unpk(acc[2 * j]);
        float2 f1 = unpk(acc[2 * j + 1]);
        *(float4*)(oa + j * 4) = make_float4(f0.x, f0.y, f1.x, f1.y);
        float2 g0 = unpk(acc[8 + 2 * j]);
        float2 g1 = unpk(acc[8 + 2 * j + 1]);
        *(float4*)(ob + j * 4) = make_float4(g0.x, g0.y, g1.x, g1.y);
    }
}

// ---------------- matvec: 8 outputs x 2 tokens, shared weight loads ----------
__device__ __forceinline__ void mm8x2(const float* __restrict__ inA,
                                      const float* __restrict__ inB,
                                      const float* __restrict__ w,
                                      int sub, ull accA[4], ull accB[4]) {
#pragma unroll 8
    for (int h = 0; h < 64; h++) {
        ull ia = pk2(inA[h]);
        ull ib = pk2(inB[h]);
        const ulonglong2* wr = (const ulonglong2*)(w + h * 64);
        ulonglong2 w0 = wr[sub];
        ulonglong2 w1 = wr[sub + 8];
        accA[0] = fma2(ia, w0.x, accA[0]);
        accA[1] = fma2(ia, w0.y, accA[1]);
        accA[2] = fma2(ia, w1.x, accA[2]);
        accA[3] = fma2(ia, w1.y, accA[3]);
        accB[0] = fma2(ib, w0.x, accB[0]);
        accB[1] = fma2(ib, w0.y, accB[1]);
        accB[2] = fma2(ib, w1.x, accB[2]);
        accB[3] = fma2(ib, w1.y, accB[3]);
    }
}
__device__ __forceinline__ void bias_init8(const float* __restrict__ bias,
                                           int sub, ull acc[4]) {
    const ulonglong2* bp = (const ulonglong2*)(bias + sub * 8);
    ulonglong2 b0 = __ldg(bp), b1 = __ldg(bp + 1);
    acc[0] = b0.x; acc[1] = b0.y; acc[2] = b1.x; acc[3] = b1.y;
}
__device__ __forceinline__ void unpack8(const ull acc[4], float o[8]) {
#pragma unroll
    for (int j = 0; j < 4; j++) {
        float2 f = unpk(acc[j]);
        o[2 * j] = f.x; o[2 * j + 1] = f.y;
    }
}

// ---------------- K5: conv + GLU + matmul chain (2 tokens/thread) ------------
// weight smem filled via cp.async, hidden behind the conv stage.
#define SMEM_POST 152832

__global__ void __launch_bounds__(256) k_post(
    const float* __restrict__ conv_sh,
    const float* __restrict__ W_pxx,    const float* __restrict__ b_pxx,
    const float* __restrict__ W_dte,    const float* __restrict__ b_dte,
    const float* __restrict__ W_dteall, const float* __restrict__ b_dteall,
    const float* __restrict__ W_fmod,   const float* __restrict__ b_fmod,
    const float* __restrict__ W_fx,     const float* __restrict__ b_fx,
    const float* __restrict__ W_fxx,    const float* __restrict__ b_fxx,
    float* __restrict__ d_out) {
    extern __shared__ float sm[];
    float* s_pxx    = sm;
    float* s_dte    = sm + 4096;
    float* s_dteall = sm + 8192;
    float* s_fmod   = sm + 12288;
    float* s_fx     = sm + 16384;
    float* s_fxx    = sm + 20480;
    float* s_cv     = sm + 24576;
    float* sA       = sm + 25152;
    float* sB       = sA + 4352;
    float* sC       = sB + 4352;
    uint32_t sb = smem_u32(sm);

    int tid = threadIdx.x;
    // issue async weight loads (chunk-transposed destinations), no wait yet
    {
        const float* wsrc[6] = {W_pxx, W_dte, W_dteall, W_fmod, W_fx, W_fxx};
#pragma unroll
        for (int m = 0; m < 6; m++)
#pragma unroll
            for (int i = 0; i < 4; i++) {
                int idx = tid + i * 256;
                int row = idx >> 4, il = idx & 15;
                int p = (il >> 1) | ((il & 1) << 3);
                CP_ASYNC16(sb + (uint32_t)(m * 4096 + row * 64 + p * 4) * 4u,
                           (const uint4*)wsrc[m] + idx);
            }
        CP_COMMIT();
        for (int i = tid; i < 576; i += 256) {
            int tap = i >> 6, h = i & 63;
            s_cv[i] = conv_sh[h * 9 + tap];
        }
    }
    __syncthreads();   // s_cv visible (weights still in flight)

    int tok = tid >> 3, sub = tid & 7;
    int ta = blockIdx.x * 64 + tok;
    int tb = ta + 32;
    float* rAa = sA + tok * 68;
    float* rBa = sB + tok * 68;
    float* rCa = sC + tok * 68;
    float* rAb = sA + (tok + 32) * 68;
    float* rBb = sB + (tok + 32) * 68;
    float* rCb = sC + (tok + 32) * 68;
    int h0 = sub * 8;

    *(float4*)(rCa + h0)     = *(const float4*)(g_Y + (size_t)ta * 64 + h0);
    *(float4*)(rCa + h0 + 4) = *(const float4*)(g_Y + (size_t)ta * 64 + h0 + 4);
    *(float4*)(rCb + h0)     = *(const float4*)(g_Y + (size_t)tb * 64 + h0);
    *(float4*)(rCb + h0 + 4) = *(const float4*)(g_Y + (size_t)tb * 64 + h0 + 4);

    // stage 1: conv (uses only s_cv) — weight cp.async still landing
#pragma unroll
    for (int tt = 0; tt < 2; tt++) {
        int t = tt ? tb : ta;
        float* rA = tt ? rAb : rAa;
        int l = t & 255, ii = l >> 4, jj = l & 15;
        float4 a0 = make_float4(0.f, 0.f, 0.f, 0.f);
        float4 a1 = make_float4(0.f, 0.f, 0.f, 0.f);
#pragma unroll
        for (int tap = 0; tap < 9; tap++) {
            int di = tap / 3 - 1, dj = tap % 3 - 1;
            int ni = ii + di, nj = jj + dj;
            if (ni < 0 || ni > 15 || nj < 0 || nj > 15) continue;
            const float* np = g_T + (size_t)(t + di * 16 + dj) * 128 + h0;
            float4 v0 = *(const float4*)np;
            float4 v1 = *(const float4*)(np + 4);
            float4 w0 = *(const float4*)(s_cv + tap * 64 + h0);
            float4 w1 = *(const float4*)(s_cv + tap * 64 + h0 + 4);
            a0 = f4add(a0, f4mul(v0, w0));
            a1 = f4add(a1, f4mul(v1, w1));
        }
        float4 t20 = *(const float4*)(g_T + (size_t)t * 128 + 64 + h0);
        float4 t21 = *(const float4*)(g_T + (size_t)t * 128 + 64 + h0 + 4);
        *(float4*)(rA + h0)     = f4mul(gelu4(a0), t20);
        *(float4*)(rA + h0 + 4) = f4mul(gelu4(a1), t21);
    }
    CP_WAIT0();        // weights landed
    __syncthreads();   // rA + weights visible to all

    {
        ull aa[4], ab[4];
        bias_init8(b_pxx, sub, aa);
#pragma unroll
        for (int j = 0; j < 4; j++) ab[j] = aa[j];
        mm8x2(rAa, rAb, s_pxx, sub, aa, ab);
        float oa[8], ob[8];
        unpack8(aa, oa); unpack8(ab, ob);
        float4 s0 = *(const float4*)(g_SH + (size_t)ta * 64 + h0);
        float4 s1 = *(const float4*)(g_SH + (size_t)ta * 64 + h0 + 4);
        *(float4*)(rBa + h0)     = f4add(*(float4*)oa, s0);
        *(float4*)(rBa + h0 + 4) = f4add(*(float4*)(oa + 4), s1);
        float4 u0 = *(const float4*)(g_SH + (size_t)tb * 64 + h0);
        float4 u1 = *(const float4*)(g_SH + (size_t)tb * 64 + h0 + 4);
        *(float4*)(rBb + h0)     = f4add(*(float4*)ob, u0);
        *(float4*)(rBb + h0 + 4) = f4add(*(float4*)(ob + 4), u1);
    }
    __syncwarp();

    {
        ull aa[4], ab[4];
        bias_init8(b_dte, sub, aa);
#pragma unroll
        for (int j = 0; j < 4; j++) ab[j] = aa[j];
        mm8x2(rCa, rCb, s_dte, sub, aa, ab);
        mm8x2(rBa, rBb, s_dteall, sub, aa, ab);
        float oa[8], ob[8];
        unpack8(aa, oa); unpack8(ab, ob);
#pragma unroll
        for (int u = 0; u < 8; u++) {
            float bd = __ldg(b_dteall + h0 + u);
            oa[u] = gelu1(oa[u] + bd);
            ob[u] = gelu1(ob[u] + bd);
        }
        *(float4*)(rAa + h0)     = *(float4*)oa;
        *(float4*)(rAa + h0 + 4) = *(float4*)(oa + 4);
        *(float4*)(rAb + h0)     = *(float4*)ob;
        *(float4*)(rAb + h0 + 4) = *(float4*)(ob + 4);
    }
    __syncwarp();

    float rgva[8], rgvb[8];
    {
        ull aa[4], ab[4];
        bias_init8(b_fmod, sub, aa);
#pragma unroll
        for (int j = 0; j < 4; j++) ab[j] = aa[j];
        mm8x2(rAa, rAb, s_fmod, sub, aa, ab);
        float oa[8], ob[8];
        unpack8(aa, oa); unpack8(ab, ob);
#pragma unroll
        for (int u = 0; u < 8; u++) { oa[u] = gelu1(oa[u]); ob[u] = gelu1(ob[u]); }
        *(float4*)(rBa + h0)     = *(float4*)oa;
        *(float4*)(rBa + h0 + 4) = *(float4*)(oa + 4);
        *(float4*)(rBb + h0)     = *(float4*)ob;
        *(float4*)(rBb + h0 + 4) = *(float4*)(ob + 4);
        *(float4*)rgva       = *(const float4*)(g_RGB + (size_t)ta * 64 + h0);
        *(float4*)(rgva + 4) = *(const float4*)(g_RGB + (size_t)ta * 64 + h0 + 4);
        *(float4*)rgvb       = *(const float4*)(g_RGB + (size_t)tb * 64 + h0);
        *(float4*)(rgvb + 4) = *(const float4*)(g_RGB + (size_t)tb * 64 + h0 + 4);
#pragma unroll
        for (int u = 0; u < 8; u++) {
            rCa[h0 + u] = gelu1(rgva[u]);
            rCb[h0 + u] = gelu1(rgvb[u]);
        }
    }
    __syncwarp();

    {
        ull aa[4], ab[4];
        bias_init8(b_fx, sub, aa);
#pragma unroll
        for (int j = 0; j < 4; j++) ab[j] = aa[j];
        mm8x2(rCa, rCb, s_fx, sub, aa, ab);
        float oa[8], ob[8];
        unpack8(aa, oa); unpack8(ab, ob);
#pragma unroll
        for (int u = 0; u < 8; u++) {
            oa[u] *= rBa[h0 + u];
            ob[u] *= rBb[h0 + u];
        }
        *(float4*)(rAa + h0)     = *(float4*)oa;
        *(float4*)(rAa + h0 + 4) = *(float4*)(oa + 4);
        *(float4*)(rAb + h0)     = *(float4*)ob;
        *(float4*)(rAb + h0 + 4) = *(float4*)(ob + 4);
    }
    __syncwarp();

    {
        ull aa[4], ab[4];
        bias_init8(b_fxx, sub, aa);
#pragma unroll
        for (int j = 0; j < 4; j++) ab[j] = aa[j];
        mm8x2(rAa, rAb, s_fxx, sub, aa, ab);
        float oa[8], ob[8];
        unpack8(aa, oa); unpack8(ab, ob);
        float4 o0 = f4add(*(float4*)oa, *(float4*)rgva);
        float4 o1 = f4add(*(float4*)(oa + 4), *(float4*)(rgva + 4));
        *(float4*)(d_out + (size_t)ta * 64 + h0)     = o0;
        *(float4*)(d_out + (size_t)ta * 64 + h0 + 4) = o1;
        float4 p0 = f4add(*(float4*)ob, *(float4*)rgvb);
        float4 p1 = f4add(*(float4*)(ob + 4), *(float4*)(rgvb + 4));
        *(float4*)(d_out + (size_t)tb * 64 + h0)     = p0;
        *(float4*)(d_out + (size_t)tb * 64 + h0 + 4) = p1;
    }
}

// ---------------- host launcher ----------------
extern "C" void kernel_launch(void* const* d_in, const int* in_sizes, int n_in,
                              void* d_out, int out_size) {
    const float* x        = (const float*)d_in[0];
    const float* dte      = (const float*)d_in[1];
    const float* w_gate   = (const float*)d_in[2];
    const float* W_exp    = (const float*)d_in[3];
    const float* b_exp    = (const float*)d_in[4];
    const float* W_sh     = (const float*)d_in[5];
    const float* b_sh     = (const float*)d_in[6];
    const float* ln_g     = (const float*)d_in[7];
    const float* ln_b     = (const float*)d_in[8];
    const float* W_px     = (const float*)d_in[9];
    const float* b_px     = (const float*)d_in[10];
    const float* conv_sh  = (const float*)d_in[11];
    const float* W_pxx    = (const float*)d_in[12];
    const float* b_pxx    = (const float*)d_in[13];
    const float* W_dte    = (const float*)d_in[14];
    const float* b_dte    = (const float*)d_in[15];
    const float* W_dteall = (const float*)d_in[16];
    const float* b_dteall = (const float*)d_in[17];
    const float* W_rgb    = (const float*)d_in[18];
    const float* b_rgb    = (const float*)d_in[19];
    const float* W_fx     = (const float*)d_in[20];
    const float* b_fx     = (const float*)d_in[21];
    const float* W_fmod   = (const float*)d_in[22];
    const float* b_fmod   = (const float*)d_in[23];
    const float* W_fxx    = (const float*)d_in[24];
    const float* b_fxx    = (const float*)d_in[25];
    float* out = (float*)d_out;

    cudaFuncSetAttribute(k_gemm, cudaFuncAttributeMaxDynamicSharedMemorySize, SMEM_MM);
    cudaFuncSetAttribute(k_preln, cudaFuncAttributeMaxDynamicSharedMemorySize, 50176);
    cudaFuncSetAttribute(k_post, cudaFuncAttributeMaxDynamicSharedMemorySize, SMEM_POST);

    k_mean<<<NT / 8, 256>>>(dte);
    k_gate2<<<Bq, 256>>>(w_gate, b_exp);
    k_wprep<<<dim3(24, 66), 256>>>(W_exp, W_sh, W_rgb, out, out_size - 1);

    k_gemm<<<512, 256, SMEM_MM>>>(dte, x, b_sh, b_rgb);

    k_preln<<<256, 256, 50176>>>(W_px, b_px, ln_g, ln_b);
    k_post<<<256, 256, SMEM_POST>>>(conv_sh,
                                    W_pxx, b_pxx, W_dte, b_dte, W_dteall, b_dteall,
                                    W_fmod, b_fmod, W_fx, b_fx, W_fxx, b_fxx,
                                    out);
}

// round 17
// speedup vs baseline: 1.1574x; 1.0761x over previous
#include <cuda_runtime.h>
#include <cuda_bf16.h>
#include <math.h>
#include <stdint.h>

#define Bq   64
#define Lq   256
#define DINq 768
#define Hq   64
#define Eq   8
#define NT   (Bq * Lq)

typedef unsigned long long ull;

// ---------------- device scratch ----------------
__device__ float g_mean[NT];
__device__ int   g_e1[Bq], g_e2[Bq];
__device__ float g_g1[Bq], g_g2[Bq];
__device__ float g_gbias[Bq * Hq];
__device__ float g_Y  [NT * Hq];
__device__ float g_SH [NT * Hq];
__device__ float g_RGB[NT * Hq];
__device__ float g_T  [NT * 2 * Hq];
// pre-converted bf16 hi/lo weights (uint4 = 8 bf16)
__device__ uint4 g_WcombH[Bq * 6144];
__device__ uint4 g_WcombL[Bq * 6144];
__device__ uint4 g_WshH[6144],  g_WshL[6144];
__device__ uint4 g_WrgbH[6144], g_WrgbL[6144];

// ---------------- helpers ----------------
__device__ __forceinline__ float gelu1(float x) {
    return 0.5f * x * (1.0f + erff(x * 0.7071067811865475f));
}
__device__ __forceinline__ float4 f4add(float4 a, float4 b) {
    return make_float4(a.x + b.x, a.y + b.y, a.z + b.z, a.w + b.w);
}
__device__ __forceinline__ float4 f4mul(float4 a, float4 b) {
    return make_float4(a.x * b.x, a.y * b.y, a.z * b.z, a.w * b.w);
}
__device__ __forceinline__ float4 gelu4(float4 a) {
    return make_float4(gelu1(a.x), gelu1(a.y), gelu1(a.z), gelu1(a.w));
}
__device__ __forceinline__ uint32_t smem_u32(const void* p) {
    uint32_t a;
    asm("{ .reg .u64 t; cvta.to.shared.u64 t, %1; cvt.u32.u64 %0, t; }"
        : "=r"(a) : "l"(p));
    return a;
}
__device__ __forceinline__ uint32_t swz(uint32_t off) {
    return off ^ ((off >> 3) & 0x70u);
}
__device__ __forceinline__ uint32_t pack_split(float f0, float f1, uint32_t& lo) {
    __nv_bfloat16 h0 = __float2bfloat16(f0);
    __nv_bfloat16 h1 = __float2bfloat16(f1);
    __nv_bfloat16 l0 = __float2bfloat16(f0 - __bfloat162float(h0));
    __nv_bfloat16 l1 = __float2bfloat16(f1 - __bfloat162float(h1));
    lo = ((uint32_t)__bfloat16_as_ushort(l1) << 16) | (uint32_t)__bfloat16_as_ushort(l0);
    return ((uint32_t)__bfloat16_as_ushort(h1) << 16) | (uint32_t)__bfloat16_as_ushort(h0);
}
__device__ __forceinline__ void ldsm_x4(uint32_t addr, uint32_t r[4]) {
    asm volatile("ldmatrix.sync.aligned.m8n8.x4.shared.b16 {%0,%1,%2,%3}, [%4];"
                 : "=r"(r[0]), "=r"(r[1]), "=r"(r[2]), "=r"(r[3]) : "r"(addr));
}
__device__ __forceinline__ void ldsm_x4_t(uint32_t addr, uint32_t r[4]) {
    asm volatile("ldmatrix.sync.aligned.m8n8.x4.trans.shared.b16 {%0,%1,%2,%3}, [%4];"
                 : "=r"(r[0]), "=r"(r[1]), "=r"(r[2]), "=r"(r[3]) : "r"(addr));
}
__device__ __forceinline__ void mma_bf16(float c[4], const uint32_t a[4],
                                         uint32_t b0, uint32_t b1) {
    asm volatile(
        "mma.sync.aligned.m16n8k16.row.col.f32.bf16.bf16.f32 "
        "{%0,%1,%2,%3}, {%4,%5,%6,%7}, {%8,%9}, {%0,%1,%2,%3};"
        : "+f"(c[0]), "+f"(c[1]), "+f"(c[2]), "+f"(c[3])
        : "r"(a[0]), "r"(a[1]), "r"(a[2]), "r"(a[3]), "r"(b0), "r"(b1));
}
#define CP_ASYNC16(saddr, gptr) \
    asm volatile("cp.async.cg.shared.global [%0], [%1], 16;" \
                 :: "r"(saddr), "l"(gptr) : "memory")
#define CP_COMMIT() asm volatile("cp.async.commit_group;" ::: "memory")
#define CP_WAIT0()  asm volatile("cp.async.wait_group 0;" ::: "memory")
// packed f32x2
__device__ __forceinline__ ull fma2(ull a, ull b, ull c) {
    ull d;
    asm("fma.rn.f32x2 %0, %1, %2, %3;" : "=l"(d) : "l"(a), "l"(b), "l"(c));
    return d;
}
__device__ __forceinline__ ull pk2(float x) {
    ull r; unsigned u = __float_as_uint(x);
    asm("mov.b64 %0, {%1, %1};" : "=l"(r) : "r"(u));
    return r;
}
__device__ __forceinline__ float2 unpk(ull v) {
    unsigned lo, hi;
    asm("mov.b64 {%0, %1}, %2;" : "=r"(lo), "=r"(hi) : "l"(v));
    return make_float2(__uint_as_float(lo), __uint_as_float(hi));
}

// ---------------- K0: row mean ----------------
__global__ void k_mean(const float* __restrict__ dte) {
    int w = threadIdx.x >> 5, lane = threadIdx.x & 31;
    int row = blockIdx.x * 8 + w;
    const float* p = dte + (size_t)row * DINq + lane;
    float s = 0.0f;
#pragma unroll
    for (int k = 0; k < DINq / 32; k++) s += p[k * 32];
#pragma unroll
    for (int o = 16; o; o >>= 1) s += __shfl_xor_sync(0xffffffffu, s, o);
    if (lane == 0) g_mean[row] = s * (1.0f / (float)DINq);
}

// ---------------- K1: gating per batch (64 blocks x 256 thr) ----------------
__global__ void k_gate2(const float* __restrict__ w_gate,
                        const float* __restrict__ b_exp) {
    __shared__ float red[8][Eq];
    __shared__ float s_lg[Eq];
    __shared__ int   s_e[2];
    __shared__ float s_g[2];
    int b = blockIdx.x, tid = threadIdx.x;
    int wid = tid >> 5, lane = tid & 31;

    float m = g_mean[b * Lq + tid];
    float lg[Eq];
#pragma unroll
    for (int e = 0; e < Eq; e++) lg[e] = m * __ldg(w_gate + tid * Eq + e);
#pragma unroll
    for (int e = 0; e < Eq; e++) {
#pragma unroll
        for (int o = 16; o; o >>= 1)
            lg[e] += __shfl_xor_sync(0xffffffffu, lg[e], o);
    }
    if (lane == 0)
#pragma unroll
        for (int e = 0; e < Eq; e++) red[wid][e] = lg[e];
    __syncthreads();

    if (tid < Eq) {
        float s = 0.0f;
#pragma unroll
        for (int w = 0; w < 8; w++) s += red[w][tid];
        s_lg[tid] = s;
    }
    __syncthreads();

    if (tid == 0) {
        int e1 = 0;
        for (int e = 1; e < Eq; e++) if (s_lg[e] > s_lg[e1]) e1 = e;
        int e2 = -1;
        for (int e = 0; e < Eq; e++) {
            if (e == e1) continue;
            if (e2 < 0 || s_lg[e] > s_lg[e2]) e2 = e;
        }
        float ex = expf(s_lg[e2] - s_lg[e1]);
        float den = 1.0f / (1.0f + ex);
        float g1 = den, g2 = ex * den;
        g_e1[b] = e1; g_e2[b] = e2; g_g1[b] = g1; g_g2[b] = g2;
        s_e[0] = e1; s_e[1] = e2; s_g[0] = g1; s_g[1] = g2;
    }
    __syncthreads();
    if (tid < Hq)
        g_gbias[b * Hq + tid] = s_g[0] * b_exp[s_e[0] * Hq + tid]
                              + s_g[1] * b_exp[s_e[1] * Hq + tid];
}

// ---------------- K2: weight prep (comb + static + loss) ----------------
__global__ void k_wprep(const float* __restrict__ W_exp,
                        const float* __restrict__ W_sh,
                        const float* __restrict__ W_rgb,
                        float* __restrict__ d_out, int loss_idx) {
    int y = blockIdx.y;
    int idx = blockIdx.x * 256 + threadIdx.x;     // < 6144
    if (y == 64 && blockIdx.x == 0 && threadIdx.x == 0) {
        float imp[Eq], ld[Eq];
#pragma unroll
        for (int e = 0; e < Eq; e++) { imp[e] = 0.0f; ld[e] = 0.0f; }
        for (int b = 0; b < Bq; b++) {
            imp[g_e1[b]] += g_g1[b];
            imp[g_e2[b]] += g_g2[b];
            ld[g_e1[b]] += 1.0f;
            ld[g_e2[b]] += 1.0f;
        }
        float m1 = 0.0f, m2 = 0.0f;
        for (int e = 0; e < Eq; e++) { m1 += imp[e]; m2 += ld[e]; }
        m1 *= (1.0f / Eq); m2 *= (1.0f / Eq);
        float var1 = 0.0f, var2 = 0.0f;
        for (int e = 0; e < Eq; e++) {
            float d1 = imp[e] - m1; var1 += d1 * d1;
            float d2 = ld[e] - m2;  var2 += d2 * d2;
        }
        var1 *= (1.0f / (Eq - 1)); var2 *= (1.0f / (Eq - 1));
        d_out[loss_idx] = 0.01f * (var1 / (m1 * m1 + 1e-10f) +
                                   var2 / (m2 * m2 + 1e-10f));
    }
    float f[8];
    if (y < Bq) {
        float g1 = g_g1[y], g2 = g_g2[y];
        const float* p1 = W_exp + (size_t)g_e1[y] * DINq * Hq + (size_t)idx * 8;
        const float* p2 = W_exp + (size_t)g_e2[y] * DINq * Hq + (size_t)idx * 8;
        float4 a0 = *(const float4*)p1, a1 = *(const float4*)(p1 + 4);
        float4 c0 = *(const float4*)p2, c1 = *(const float4*)(p2 + 4);
        f[0] = g1 * a0.x + g2 * c0.x; f[1] = g1 * a0.y + g2 * c0.y;
        f[2] = g1 * a0.z + g2 * c0.z; f[3] = g1 * a0.w + g2 * c0.w;
        f[4] = g1 * a1.x + g2 * c1.x; f[5] = g1 * a1.y + g2 * c1.y;
        f[6] = g1 * a1.z + g2 * c1.z; f[7] = g1 * a1.w + g2 * c1.w;
    } else {
        const float* src = (y == 65 ? W_rgb : W_sh) + (size_t)idx * 8;
        float4 a0 = *(const float4*)src, a1 = *(const float4*)(src + 4);
        f[0] = a0.x; f[1] = a0.y; f[2] = a0.z; f[3] = a0.w;
        f[4] = a1.x; f[5] = a1.y; f[6] = a1.z; f[7] = a1.w;
    }
    uint32_t hu[4], lu[4];
    hu[0] = pack_split(f[0], f[1], lu[0]);
    hu[1] = pack_split(f[2], f[3], lu[1]);
    hu[2] = pack_split(f[4], f[5], lu[2]);
    hu[3] = pack_split(f[6], f[7], lu[3]);
    uint4 h4 = make_uint4(hu[0], hu[1], hu[2], hu[3]);
    uint4 l4 = make_uint4(lu[0], lu[1], lu[2], lu[3]);
    if (y < Bq)       { g_WcombH[y * 6144 + idx] = h4; g_WcombL[y * 6144 + idx] = l4; }
    else if (y == 64) { g_WshH[idx]  = h4; g_WshL[idx]  = l4; }
    else              { g_WrgbH[idx] = h4; g_WrgbL[idx] = l4; }
}

// ---------------- K3: pipelined mma.sync bf16x3 GEMM, M=64 tiles -------------
// R12 structure; B fragments via ldmatrix.x4.trans (halved B ldsm count)
#define BUFSZ  49152u
#define SMEM_MM (2 * 49152)

template <bool JOBA>
__device__ __forceinline__ void gemm_body(
    int job, const float* __restrict__ dte, const float* __restrict__ x,
    const float* __restrict__ b_sh, const float* __restrict__ b_rgb,
    char* smc, uint32_t sb) {
    int tid = threadIdx.x, lane = tid & 31, wid = tid >> 5;

    const float* Asrc;
    int bb = 0;
    size_t tok0;
    if (JOBA) {
        bb = job >> 2;
        tok0 = (size_t)bb * Lq + (job & 3) * 64;
        Asrc = dte + tok0 * DINq;
    } else {
        tok0 = (size_t)job * 64;
        Asrc = x + tok0 * DINq;
    }

    constexpr int NTL = JOBA ? 4 : 2;
    constexpr int NP  = NTL / 2;
    constexpr uint32_t ROWB = JOBA ? 256u : 128u;
    constexpr int RSH = JOBA ? 8 : 7;
    constexpr uint32_t OFFAL = 8192u;
    constexpr uint32_t OFFBH = 16384u;
    constexpr uint32_t OFFBL = OFFBH + (JOBA ? 16384u : 8192u);

    int wm = wid & 1, wn = wid >> 1;
    int m_base = wm * 32;
    int n_base = wn * (JOBA ? 32 : 16);

    float c[2][NTL][4];
#pragma unroll
    for (int mt = 0; mt < 2; mt++)
#pragma unroll
        for (int nt = 0; nt < NTL; nt++)
#pragma unroll
            for (int j = 0; j < 4; j++) c[mt][nt][j] = 0.0f;

    int lr = lane & 7, sel = lane >> 3;
    int a_row_off = ((sel & 1) << 3) + lr;
    int a_kb_off  = (sel >> 1) << 4;
    int brow = lane & 15;
    uint32_t ncolb = (uint32_t)((lane >> 4) << 3) * 2u;   // +8 cols for hi half

    int arow = tid >> 2, akseg = tid & 3;
    const float* asrc_t = Asrc + (size_t)arow * DINq + akseg * 16;
    float areg[16];

    auto issueB = [&](int ch, uint32_t bo) {
        int k0 = ch * 64;
        if (JOBA) {
#pragma unroll
            for (int i = 0; i < 8; i++) {
                int t2 = tid + i * 256;
                int reg = t2 >> 10;
                int r = t2 & 1023;
                int k = r >> 4, seg = r & 15;
                const uint4* g;
                if (seg < 8)
                    g = (reg ? g_WcombL : g_WcombH) + bb * 6144 + (k0 + k) * 8 + seg;
                else
                    g = (reg ? g_WshL : g_WshH) + (k0 + k) * 8 + (seg - 8);
                uint32_t off = (uint32_t)k * ROWB + (uint32_t)seg * 16u;
                off ^= ((off >> RSH) & 7u) << 4;
                CP_ASYNC16(sb + bo + (reg ? OFFBL : OFFBH) + off, g);
            }
        } else {
#pragma unroll
            for (int i = 0; i < 4; i++) {
                int t2 = tid + i * 256;
                int reg = t2 >> 9;
                int r = t2 & 511;
                int k = r >> 3, seg = r & 7;
                const uint4* g = (reg ? g_WrgbL : g_WrgbH) + (k0 + k) * 8 + seg;
                uint32_t off = (uint32_t)k * ROWB + (uint32_t)seg * 16u;
                off ^= ((off >> RSH) & 7u) << 4;
                CP_ASYNC16(sb + bo + (reg ? OFFBL : OFFBH) + off, g);
            }
        }
        CP_COMMIT();
    };
    auto ldgA = [&](int ch) {
        const float* s = asrc_t + ch * 64;
#pragma unroll
        for (int j = 0; j < 4; j++)
            *(float4*)(areg + j * 4) = *(const float4*)(s + j * 4);
    };

    issueB(0, 0u);
    ldgA(0);

    for (int ch = 0; ch < 12; ch++) {
        uint32_t bo = (ch & 1) ? BUFSZ : 0u;

        {
            uint32_t hu[8], lu[8];
#pragma unroll
            for (int j = 0; j < 4; j++) {
                hu[j * 2]     = pack_split(areg[j * 4],     areg[j * 4 + 1], lu[j * 2]);
                hu[j * 2 + 1] = pack_split(areg[j * 4 + 2], areg[j * 4 + 3], lu[j * 2 + 1]);
            }
            uint32_t base = (uint32_t)arow * 128u + (uint32_t)akseg * 32u;
            uint32_t o0 = swz(base), o1 = swz(base + 16u);
            *(uint4*)(smc + bo + o0) = make_uint4(hu[0], hu[1], hu[2], hu[3]);
            *(uint4*)(smc + bo + o1) = make_uint4(hu[4], hu[5], hu[6], hu[7]);
            *(uint4*)(smc + bo + OFFAL + o0) = make_uint4(lu[0], lu[1], lu[2], lu[3]);
            *(uint4*)(smc + bo + OFFAL + o1) = make_uint4(lu[4], lu[5], lu[6], lu[7]);
        }
        CP_WAIT0();
        __syncthreads();

        if (ch < 11) {
            issueB(ch + 1, (ch & 1) ? 0u : BUFSZ);
            ldgA(ch + 1);
        }

#pragma unroll
        for (int ks = 0; ks < 4; ks++) {
            int kbyte = ks * 32;
            uint32_t ahi[2][4], alo[2][4];
#pragma unroll
            for (int mt = 0; mt < 2; mt++) {
                uint32_t ro = (uint32_t)((m_base + mt * 16 + a_row_off) * 128
                                         + kbyte + a_kb_off);
                uint32_t so = swz(ro);
                ldsm_x4(sb + bo + so, ahi[mt]);
                ldsm_x4(sb + bo + OFFAL + so, alo[mt]);
            }
            uint32_t krow = (uint32_t)(ks * 16 + brow) * ROWB;
#pragma unroll
            for (int p = 0; p < NP; p++) {
                uint32_t boff = krow + ncolb + (uint32_t)(n_base + p * 16) * 2u;
                boff ^= ((boff >> RSH) & 7u) << 4;
                uint32_t bh[4], bl[4];
                ldsm_x4_t(sb + bo + OFFBH + boff, bh);
                ldsm_x4_t(sb + bo + OFFBL + boff, bl);
#pragma unroll
                for (int mt = 0; mt < 2; mt++) {
                    mma_bf16(c[mt][2 * p],     ahi[mt], bh[0], bh[1]);
                    mma_bf16(c[mt][2 * p],     ahi[mt], bl[0], bl[1]);
                    mma_bf16(c[mt][2 * p],     alo[mt], bh[0], bh[1]);
                    mma_bf16(c[mt][2 * p + 1], ahi[mt], bh[2], bh[3]);
                    mma_bf16(c[mt][2 * p + 1], ahi[mt], bl[2], bl[3]);
                    mma_bf16(c[mt][2 * p + 1], alo[mt], bh[2], bh[3]);
                }
            }
        }
    }

    int rg = lane >> 2, tg = lane & 3;
#pragma unroll
    for (int mt = 0; mt < 2; mt++) {
#pragma unroll
        for (int nt = 0; nt < NTL; nt++) {
            int col = n_base + nt * 8 + tg * 2;
            int row0 = m_base + mt * 16 + rg;
            float* dst;
            const float* bias;
            int cc;
            if (!JOBA) {
                dst = g_RGB; bias = b_rgb; cc = col;
            } else if (col < 64) {
                dst = g_Y; bias = g_gbias + bb * 64; cc = col;
            } else {
                dst = g_SH; bias = b_sh; cc = col - 64;
            }
            float b0 = bias[cc], b1 = bias[cc + 1];
            float* p0 = dst + (tok0 + row0) * Hq + cc;
            float* p1 = dst + (tok0 + row0 + 8) * Hq + cc;
            p0[0] = c[mt][nt][0] + b0;  p0[1] = c[mt][nt][1] + b1;
            p1[0] = c[mt][nt][2] + b0;  p1[1] = c[mt][nt][3] + b1;
        }
    }
}

__global__ void __launch_bounds__(256, 2) k_gemm(
    const float* __restrict__ dte, const float* __restrict__ x,
    const float* __restrict__ b_sh, const float* __restrict__ b_rgb) {
    extern __shared__ char smc[];
    uint32_t sb = smem_u32(smc);
    int b = blockIdx.x;
    if (b & 1)
        gemm_body<false>(b >> 1, dte, x, b_sh, b_rgb, smc, sb);
    else
        gemm_body<true>(b >> 1, dte, x, b_sh, b_rgb, smc, sb);
}

// ---------------- K4: LayerNorm + W_px (8 thr/token, 2 tokens/thread) -------
__global__ void __launch_bounds__(256) k_preln(
    const float* __restrict__ W_px, const float* __restrict__ b_px,
    const float* __restrict__ ln_g, const float* __restrict__ ln_b) {
    extern __shared__ float sm[];
    float* s_w = sm;            // 64 x 128, chunk-transposed
    float* s_t = sm + 8192;     // 64 tokens x 68

    int tid = threadIdx.x;
#pragma unroll
    for (int i = 0; i < 8; i++) {
        int idx = tid + i * 256;
        int row = idx >> 5, il = idx & 31;
        int p = (il >> 2) | ((il & 3) << 3);
        ((float4*)s_w)[row * 32 + p] = ((const float4*)W_px)[idx];
    }

    int tok = tid >> 3, sub = tid & 7;
    int ta = blockIdx.x * 64 + tok;
    int tb = ta + 32;

    float va[8], vb[8];
    {
        const float* pa = g_SH + (size_t)ta * Hq + sub * 8;
        const float* pb = g_SH + (size_t)tb * Hq + sub * 8;
        *(float4*)va       = *(const float4*)pa;
        *(float4*)(va + 4) = *(const float4*)(pa + 4);
        *(float4*)vb       = *(const float4*)pb;
        *(float4*)(vb + 4) = *(const float4*)(pb + 4);
    }
    float sa = 0.f, s2a = 0.f, sbm = 0.f, s2b = 0.f;
#pragma unroll
    for (int u = 0; u < 8; u++) {
        sa += va[u]; s2a += va[u] * va[u];
        sbm += vb[u]; s2b += vb[u] * vb[u];
    }
#pragma unroll
    for (int o = 1; o < 8; o <<= 1) {
        sa  += __shfl_xor_sync(0xffffffffu, sa, o);
        s2a += __shfl_xor_sync(0xffffffffu, s2a, o);
        sbm += __shfl_xor_sync(0xffffffffu, sbm, o);
        s2b += __shfl_xor_sync(0xffffffffu, s2b, o);
    }
    float ma = sa * (1.0f / Hq), mb = sbm * (1.0f / Hq);
    float ra = rsqrtf(s2a * (1.0f / Hq) - ma * ma + 1e-6f);
    float rb = rsqrtf(s2b * (1.0f / Hq) - mb * mb + 1e-6f);

    float* tra = s_t + tok * 68;
    float* trb = s_t + (tok + 32) * 68;
#pragma unroll
    for (int u = 0; u < 8; u++) {
        float g = __ldg(ln_g + sub * 8 + u), bv = __ldg(ln_b + sub * 8 + u);
        tra[sub * 8 + u] = (va[u] - ma) * ra * g + bv;
        trb[sub * 8 + u] = (vb[u] - mb) * rb * g + bv;
    }
    __syncthreads();

    ull acc[16];
    {
        const ulonglong2* bp = (const ulonglong2*)(b_px + sub * 16);
#pragma unroll
        for (int j = 0; j < 4; j++) {
            ulonglong2 bv = __ldg(bp + j);
            acc[2 * j] = bv.x;      acc[2 * j + 1] = bv.y;
            acc[8 + 2 * j] = bv.x;  acc[8 + 2 * j + 1] = bv.y;
        }
    }
#pragma unroll 4
    for (int h = 0; h < 64; h++) {
        ull ia = pk2(tra[h]);
        ull ib = pk2(trb[h]);
        const ulonglong2* wr = (const ulonglong2*)(s_w + h * 128);
#pragma unroll
        for (int j = 0; j < 4; j++) {
            ulonglong2 wv = wr[sub + j * 8];
            acc[2 * j]         = fma2(ia, wv.x, acc[2 * j]);
            acc[2 * j + 1]     = fma2(ia, wv.y, acc[2 * j + 1]);
            acc[8 + 2 * j]     = fma2(ib, wv.x, acc[8 + 2 * j]);
            acc[8 + 2 * j + 1] = fma2(ib, wv.y, acc[8 + 2 * j + 1]);
        }
    }
    float* oa = g_T + (size_t)ta * 128 + sub * 16;
    float* ob = g_T + (size_t)tb * 128 + sub * 16;
#pragma unroll
    for (int j = 0; j < 4; j++) {
        float2 f0 = unpk(acc[2 * j]);
        float2 f1 = unpk(acc[2 * j + 1]);
        *(float4*)(oa + j * 4) = make_float4(f0.x, f0.y, f1.x, f1.y);
        float2 g0 = unpk(acc[8 + 2 * j]);
        float2 g1 = unpk(acc[8 + 2 * j + 1]);
        *(float4*)(ob + j * 4) = make_float4(g0.x, g0.y, g1.x, g1.y);
    }
}

// ---------------- matvec: 8 outputs x 2 tokens, shared weight loads ----------
__device__ __forceinline__ void mm8x2(const float* __restrict__ inA,
                                      const float* __restrict__ inB,
                                      const float* __restrict__ w,
                                      int sub, ull accA[4], ull accB[4]) {
#pragma unroll 8
    for (int h = 0; h < 64; h++) {
        ull ia = pk2(inA[h]);
        ull ib = pk2(inB[h]);
        const ulonglong2* wr = (const ulonglong2*)(w + h * 64);
        ulonglong2 w0 = wr[sub];
        ulonglong2 w1 = wr[sub + 8];
        accA[0] = fma2(ia, w0.x, accA[0]);
        accA[1] = fma2(ia, w0.y, accA[1]);
        accA[2] = fma2(ia, w1.x, accA[2]);
        accA[3] = fma2(ia, w1.y, accA[3]);
        accB[0] = fma2(ib, w0.x, accB[0]);
        accB[1] = fma2(ib, w0.y, accB[1]);
        accB[2] = fma2(ib, w1.x, accB[2]);
        accB[3] = fma2(ib, w1.y, accB[3]);
    }
}
__device__ __forceinline__ void bias_init8(const float* __restrict__ bias,
                                           int sub, ull acc[4]) {
    const ulonglong2* bp = (const ulonglong2*)(bias + sub * 8);
    ulonglong2 b0 = __ldg(bp), b1 = __ldg(bp + 1);
    acc[0] = b0.x; acc[1] = b0.y; acc[2] = b1.x; acc[3] = b1.y;
}
__device__ __forceinline__ void unpack8(const ull acc[4], float o[8]) {
#pragma unroll
    for (int j = 0; j < 4; j++) {
        float2 f = unpk(acc[j]);
        o[2 * j] = f.x; o[2 * j + 1] = f.y;
    }
}

// ---------------- K5: conv + GLU + matmul chain (2 tokens/thread, R12) -------
#define SMEM_POST 152832

__global__ void __launch_bounds__(256) k_post(
    const float* __restrict__ conv_sh,
    const float* __restrict__ W_pxx,    const float* __restrict__ b_pxx,
    const float* __restrict__ W_dte,    const float* __restrict__ b_dte,
    const float* __restrict__ W_dteall, const float* __restrict__ b_dteall,
    const float* __restrict__ W_fmod,   const float* __restrict__ b_fmod,
    const float* __restrict__ W_fx,     const float* __restrict__ b_fx,
    const float* __restrict__ W_fxx,    const float* __restrict__ b_fxx,
    float* __restrict__ d_out) {
    extern __shared__ float sm[];
    float* s_pxx    = sm;
    float* s_dte    = sm + 4096;
    float* s_dteall = sm + 8192;
    float* s_fmod   = sm + 12288;
    float* s_fx     = sm + 16384;
    float* s_fxx    = sm + 20480;
    float* s_cv     = sm + 24576;
    float* sA       = sm + 25152;
    float* sB       = sA + 4352;
    float* sC       = sB + 4352;

    int tid = threadIdx.x;
    {
        const float* wsrc[6] = {W_pxx, W_dte, W_dteall, W_fmod, W_fx, W_fxx};
#pragma unroll
        for (int m = 0; m < 6; m++)
#pragma unroll
            for (int i = 0; i < 4; i++) {
                int idx = tid + i * 256;
                int row = idx >> 4, il = idx & 15;
                int p = (il >> 1) | ((il & 1) << 3);
                ((float4*)(sm + m * 4096))[row * 16 + p] =
                    ((const float4*)wsrc[m])[idx];
            }
        for (int i = tid; i < 576; i += 256) {
            int tap = i >> 6, h = i & 63;
            s_cv[i] = conv_sh[h * 9 + tap];
        }
    }
    __syncthreads();

    int tok = tid >> 3, sub = tid & 7;
    int ta = blockIdx.x * 64 + tok;
    int tb = ta + 32;
    float* rAa = sA + tok * 68;
    float* rBa = sB + tok * 68;
    float* rCa = sC + tok * 68;
    float* rAb = sA + (tok + 32) * 68;
    float* rBb = sB + (tok + 32) * 68;
    float* rCb = sC + (tok + 32) * 68;
    int h0 = sub * 8;

    *(float4*)(rCa + h0)     = *(const float4*)(g_Y + (size_t)ta * 64 + h0);
    *(float4*)(rCa + h0 + 4) = *(const float4*)(g_Y + (size_t)ta * 64 + h0 + 4);
    *(float4*)(rCb + h0)     = *(const float4*)(g_Y + (size_t)tb * 64 + h0);
    *(float4*)(rCb + h0 + 4) = *(const float4*)(g_Y + (size_t)tb * 64 + h0 + 4);

#pragma unroll
    for (int tt = 0; tt < 2; tt++) {
        int t = tt ? tb : ta;
        float* rA = tt ? rAb : rAa;
        int l = t & 255, ii = l >> 4, jj = l & 15;
        float4 a0 = make_float4(0.f, 0.f, 0.f, 0.f);
        float4 a1 = make_float4(0.f, 0.f, 0.f, 0.f);
#pragma unroll
        for (int tap = 0; tap < 9; tap++) {
            int di = tap / 3 - 1, dj = tap % 3 - 1;
            int ni = ii + di, nj = jj + dj;
            if (ni < 0 || ni > 15 || nj < 0 || nj > 15) continue;
            const float* np = g_T + (size_t)(t + di * 16 + dj) * 128 + h0;
            float4 v0 = *(const float4*)np;
            float4 v1 = *(const float4*)(np + 4);
            float4 w0 = *(const float4*)(s_cv + tap * 64 + h0);
            float4 w1 = *(const float4*)(s_cv + tap * 64 + h0 + 4);
            a0 = f4add(a0, f4mul(v0, w0));
            a1 = f4add(a1, f4mul(v1, w1));
        }
        float4 t20 = *(const float4*)(g_T + (size_t)t * 128 + 64 + h0);
        float4 t21 = *(const float4*)(g_T + (size_t)t * 128 + 64 + h0 + 4);
        *(float4*)(rA + h0)     = f4mul(gelu4(a0), t20);
        *(float4*)(rA + h0 + 4) = f4mul(gelu4(a1), t21);
    }
    __syncwarp();

    {
        ull aa[4], ab[4];
        bias_init8(b_pxx, sub, aa);
#pragma unroll
        for (int j = 0; j < 4; j++) ab[j] = aa[j];
        mm8x2(rAa, rAb, s_pxx, sub, aa, ab);
        float oa[8], ob[8];
        unpack8(aa, oa); unpack8(ab, ob);
        float4 s0 = *(const float4*)(g_SH + (size_t)ta * 64 + h0);
        float4 s1 = *(const float4*)(g_SH + (size_t)ta * 64 + h0 + 4);
        *(float4*)(rBa + h0)     = f4add(*(float4*)oa, s0);
        *(float4*)(rBa + h0 + 4) = f4add(*(float4*)(oa + 4), s1);
        float4 u0 = *(const float4*)(g_SH + (size_t)tb * 64 + h0);
        float4 u1 = *(const float4*)(g_SH + (size_t)tb * 64 + h0 + 4);
        *(float4*)(rBb + h0)     = f4add(*(float4*)ob, u0);
        *(float4*)(rBb + h0 + 4) = f4add(*(float4*)(ob + 4), u1);
    }
    __syncwarp();

    {
        ull aa[4], ab[4];
        bias_init8(b_dte, sub, aa);
#pragma unroll
        for (int j = 0; j < 4; j++) ab[j] = aa[j];
        mm8x2(rCa, rCb, s_dte, sub, aa, ab);
        mm8x2(rBa, rBb, s_dteall, sub, aa, ab);
        float oa[8], ob[8];
        unpack8(aa, oa); unpack8(ab, ob);
#pragma unroll
        for (int u = 0; u < 8; u++) {
            float bd = __ldg(b_dteall + h0 + u);
            oa[u] = gelu1(oa[u] + bd);
            ob[u] = gelu1(ob[u] + bd);
        }
        *(float4*)(rAa + h0)     = *(float4*)oa;
        *(float4*)(rAa + h0 + 4) = *(float4*)(oa + 4);
        *(float4*)(rAb + h0)     = *(float4*)ob;
        *(float4*)(rAb + h0 + 4) = *(float4*)(ob + 4);
    }
    __syncwarp();

    float rgva[8], rgvb[8];
    {
        ull aa[4], ab[4];
        bias_init8(b_fmod, sub, aa);
#pragma unroll
        for (int j = 0; j < 4; j++) ab[j] = aa[j];
        mm8x2(rAa, rAb, s_fmod, sub, aa, ab);
        float oa[8], ob[8];
        unpack8(aa, oa); unpack8(ab, ob);
#pragma unroll
        for (int u = 0; u < 8; u++) { oa[u] = gelu1(oa[u]); ob[u] = gelu1(ob[u]); }
        *(float4*)(rBa + h0)     = *(float4*)oa;
        *(float4*)(rBa + h0 + 4) = *(float4*)(oa + 4);
        *(float4*)(rBb + h0)     = *(float4*)ob;
        *(float4*)(rBb + h0 + 4) = *(float4*)(ob + 4);
        *(float4*)rgva       = *(const float4*)(g_RGB + (size_t)ta * 64 + h0);
        *(float4*)(rgva + 4) = *(const float4*)(g_RGB + (size_t)ta * 64 + h0 + 4);
        *(float4*)rgvb       = *(const float4*)(g_RGB + (size_t)tb * 64 + h0);
        *(float4*)(rgvb + 4) = *(const float4*)(g_RGB + (size_t)tb * 64 + h0 + 4);
#pragma unroll
        for (int u = 0; u < 8; u++) {
            rCa[h0 + u] = gelu1(rgva[u]);
            rCb[h0 + u] = gelu1(rgvb[u]);
        }
    }
    __syncwarp();

    {
        ull aa[4], ab[4];
        bias_init8(b_fx, sub, aa);
#pragma unroll
        for (int j = 0; j < 4; j++) ab[j] = aa[j];
        mm8x2(rCa, rCb, s_fx, sub, aa, ab);
        float oa[8], ob[8];
        unpack8(aa, oa); unpack8(ab, ob);
#pragma unroll
        for (int u = 0; u < 8; u++) {
            oa[u] *= rBa[h0 + u];
            ob[u] *= rBb[h0 + u];
        }
        *(float4*)(rAa + h0)     = *(float4*)oa;
        *(float4*)(rAa + h0 + 4) = *(float4*)(oa + 4);
        *(float4*)(rAb + h0)     = *(float4*)ob;
        *(float4*)(rAb + h0 + 4) = *(float4*)(ob + 4);
    }
    __syncwarp();

    {
        ull aa[4], ab[4];
        bias_init8(b_fxx, sub, aa);
#pragma unroll
        for (int j = 0; j < 4; j++) ab[j] = aa[j];
        mm8x2(rAa, rAb, s_fxx, sub, aa, ab);
        float oa[8], ob[8];
        unpack8(aa, oa); unpack8(ab, ob);
        float4 o0 = f4add(*(float4*)oa, *(float4*)rgva);
        float4 o1 = f4add(*(float4*)(oa + 4), *(float4*)(rgva + 4));
        *(float4*)(d_out + (size_t)ta * 64 + h0)     = o0;
        *(float4*)(d_out + (size_t)ta * 64 + h0 + 4) = o1;
        float4 p0 = f4add(*(float4*)ob, *(float4*)rgvb);
        float4 p1 = f4add(*(float4*)(ob + 4), *(float4*)(rgvb + 4));
        *(float4*)(d_out + (size_t)tb * 64 + h0)     = p0;
        *(float4*)(d_out + (size_t)tb * 64 + h0 + 4) = p1;
    }
}

// ---------------- host launcher ----------------
extern "C" void kernel_launch(void* const* d_in, const int* in_sizes, int n_in,
                              void* d_out, int out_size) {
    const float* x        = (const float*)d_in[0];
    const float* dte      = (const float*)d_in[1];
    const float* w_gate   = (const float*)d_in[2];
    const float* W_exp    = (const float*)d_in[3];
    const float* b_exp    = (const float*)d_in[4];
    const float* W_sh     = (const float*)d_in[5];
    const float* b_sh     = (const float*)d_in[6];
    const float* ln_g     = (const float*)d_in[7];
    const float* ln_b     = (const float*)d_in[8];
    const float* W_px     = (const float*)d_in[9];
    const float* b_px     = (const float*)d_in[10];
    const float* conv_sh  = (const float*)d_in[11];
    const float* W_pxx    = (const float*)d_in[12];
    const float* b_pxx    = (const float*)d_in[13];
    const float* W_dte    = (const float*)d_in[14];
    const float* b_dte    = (const float*)d_in[15];
    const float* W_dteall = (const float*)d_in[16];
    const float* b_dteall = (const float*)d_in[17];
    const float* W_rgb    = (const float*)d_in[18];
    const float* b_rgb    = (const float*)d_in[19];
    const float* W_fx     = (const float*)d_in[20];
    const float* b_fx     = (const float*)d_in[21];
    const float* W_fmod   = (const float*)d_in[22];
    const float* b_fmod   = (const float*)d_in[23];
    const float* W_fxx    = (const float*)d_in[24];
    const float* b_fxx    = (const float*)d_in[25];
    float* out = (float*)d_out;

    cudaFuncSetAttribute(k_gemm, cudaFuncAttributeMaxDynamicSharedMemorySize, SMEM_MM);
    cudaFuncSetAttribute(k_preln, cudaFuncAttributeMaxDynamicSharedMemorySize, 50176);
    cudaFuncSetAttribute(k_post, cudaFuncAttributeMaxDynamicSharedMemorySize, SMEM_POST);

    k_mean<<<NT / 8, 256>>>(dte);
    k_gate2<<<Bq, 256>>>(w_gate, b_exp);
    k_wprep<<<dim3(24, 66), 256>>>(W_exp, W_sh, W_rgb, out, out_size - 1);

    k_gemm<<<512, 256, SMEM_MM>>>(dte, x, b_sh, b_rgb);

    k_preln<<<256, 256, 50176>>>(W_px, b_px, ln_g, ln_b);
    k_post<<<256, 256, SMEM_POST>>>(conv_sh,
                                    W_pxx, b_pxx, W_dte, b_dte, W_dteall, b_dteall,
                                    W_fmod, b_fmod, W_fx, b_fx, W_fxx, b_fxx,
                                    out);
}